// round 1
// baseline (speedup 1.0000x reference)
#include <cuda_runtime.h>
#include <math.h>

#define NN 60000
#define EE 300000
#define AA 8000
#define GG 256
#define DD 128
#define HH 8
#define CC 16
#define LL 3
#define RBFD 16
#define SBFD 112

// ---------------- scratch (static device globals; no allocation) ----------------
__device__ float g_featA[NN * DD];
__device__ float g_featB[NN * DD];
__device__ float g_featC[NN * DD];
__device__ float g_featD[NN * DD];
__device__ float g_featE[NN * DD];
__device__ float g_sw[(size_t)EE * DD];
__device__ float g_ex[EE * HH];
__device__ float g_alpha[EE * HH];
__device__ unsigned g_menc[NN * HH];
__device__ float g_ssum[NN * HH];
__device__ float g_at1[AA * DD];
__device__ float g_at2[AA * DD];
__device__ float g_at3[AA * DD];
__device__ float g_results[AA];
__device__ float g_gsum[GG];
__device__ float g_gvar[GG];
__device__ float g_gcnt[GG];

// ---------------- helpers ----------------
__device__ __forceinline__ unsigned fenc(float f) {
    unsigned u = __float_as_uint(f);
    return (u & 0x80000000u) ? ~u : (u | 0x80000000u);
}
__device__ __forceinline__ float fdec(unsigned u) {
    return (u & 0x80000000u) ? __uint_as_float(u ^ 0x80000000u) : __uint_as_float(~u);
}
__device__ __forceinline__ float silu_f(float v) { return v / (1.f + expf(-v)); }

// ---------------- generic GEMM with fused epilogue ----------------
// C[M,Nn] = ep(A[M,K] @ W[K,Nn] + bias)
// flags: 1 = SiLU, 2 = add res[r,c], 4 = multiply by mul[r,c]
#define BM 64
#define BN 64
#define BK 16
#define EP_SILU 1
#define EP_RES 2
#define EP_MUL 4

__global__ __launch_bounds__(256) void gemm_ep(
    const float* __restrict__ A, const float* __restrict__ W,
    const float* __restrict__ bias, const float* __restrict__ res,
    const float* __restrict__ mul, float* __restrict__ C,
    int M, int K, int Nn, int flags)
{
    __shared__ float As[BK][BM];
    __shared__ float Ws[BK][BN];
    int tid = threadIdx.x;
    int row0 = blockIdx.y * BM;
    int col0 = blockIdx.x * BN;
    int tr = tid >> 4, tc = tid & 15;

    float acc[4][4];
#pragma unroll
    for (int i = 0; i < 4; i++)
#pragma unroll
        for (int j = 0; j < 4; j++) acc[i][j] = 0.f;

    int ar = tid >> 2, ac = (tid & 3) << 2;   // A tile: 64 rows x 16 cols
    int wr = tid >> 4, wc = (tid & 15) << 2;  // W tile: 16 rows x 64 cols

    for (int k0 = 0; k0 < K; k0 += BK) {
        float4 av = make_float4(0.f, 0.f, 0.f, 0.f);
        int grow = row0 + ar;
        if (grow < M) av = *reinterpret_cast<const float4*>(A + (size_t)grow * K + (k0 + ac));
        As[ac + 0][ar] = av.x; As[ac + 1][ar] = av.y;
        As[ac + 2][ar] = av.z; As[ac + 3][ar] = av.w;

        float4 wv = make_float4(0.f, 0.f, 0.f, 0.f);
        int gcol = col0 + wc;
        if (gcol < Nn) wv = *reinterpret_cast<const float4*>(W + (size_t)(k0 + wr) * Nn + gcol);
        Ws[wr][wc + 0] = wv.x; Ws[wr][wc + 1] = wv.y;
        Ws[wr][wc + 2] = wv.z; Ws[wr][wc + 3] = wv.w;
        __syncthreads();

#pragma unroll
        for (int kk = 0; kk < BK; kk++) {
            float a[4], b[4];
#pragma unroll
            for (int i = 0; i < 4; i++) a[i] = As[kk][tr * 4 + i];
#pragma unroll
            for (int j = 0; j < 4; j++) b[j] = Ws[kk][tc * 4 + j];
#pragma unroll
            for (int i = 0; i < 4; i++)
#pragma unroll
                for (int j = 0; j < 4; j++) acc[i][j] += a[i] * b[j];
        }
        __syncthreads();
    }

#pragma unroll
    for (int i = 0; i < 4; i++) {
        int r = row0 + tr * 4 + i;
        if (r >= M) continue;
#pragma unroll
        for (int j = 0; j < 4; j++) {
            int c = col0 + tc * 4 + j;
            if (c >= Nn) continue;
            float v = acc[i][j];
            if (bias) v += bias[c];
            if (flags & EP_SILU) v = silu_f(v);
            if (flags & EP_RES) v += res[(size_t)r * Nn + c];
            if (flags & EP_MUL) v *= mul[(size_t)r * Nn + c];
            C[(size_t)r * Nn + c] = v;
        }
    }
}

// ---------------- scatter / attention / norm kernels ----------------
__global__ void scatter_rows(const float* __restrict__ src, const int* __restrict__ idx,
                             float* __restrict__ dst, int rows) {
    int t = blockIdx.x * blockDim.x + threadIdx.x;
    if (t >= rows * DD) return;
    int n = t >> 7, d = t & 127;
    atomicAdd(&dst[(size_t)idx[n] * DD + d], src[t]);
}

__global__ void attn_logit(const float* __restrict__ q, const float* __restrict__ k,
                           const float* __restrict__ ekat, const int* __restrict__ eidx,
                           const int* __restrict__ pai, float* __restrict__ logit,
                           unsigned* __restrict__ menc) {
    int t = blockIdx.x * blockDim.x + threadIdx.x;
    if (t >= EE * HH) return;
    int e = t >> 3, h = t & 7;
    int src = eidx[e], dst = eidx[EE + e], pa = pai[e];
    const float4* qp = (const float4*)(q + (size_t)dst * DD + h * CC);
    const float4* kp = (const float4*)(k + (size_t)src * DD + h * CC);
    const float4* ep = (const float4*)(ekat + (size_t)pa * DD + h * CC);
    float s = 0.f;
#pragma unroll
    for (int i = 0; i < 4; i++) {
        float4 a = qp[i], b = kp[i], c = ep[i];
        s += a.x * (b.x + c.x) + a.y * (b.y + c.y) + a.z * (b.z + c.z) + a.w * (b.w + c.w);
    }
    s *= 0.25f;  // 1/sqrt(C), C=16
    logit[t] = s;
    atomicMax(&menc[dst * HH + h], fenc(s));
}

__global__ void attn_exp(float* __restrict__ ex, const int* __restrict__ eidx,
                         const unsigned* __restrict__ menc, float* __restrict__ ssum) {
    int t = blockIdx.x * blockDim.x + threadIdx.x;
    if (t >= EE * HH) return;
    int e = t >> 3, h = t & 7;
    int dst = eidx[EE + e];
    float mm = fdec(menc[dst * HH + h]);
    float v = expf(ex[t] - mm);
    ex[t] = v;
    atomicAdd(&ssum[dst * HH + h], v);
}

__global__ void attn_alpha(const float* __restrict__ ex, const int* __restrict__ eidx,
                           const float* __restrict__ ssum, float* __restrict__ alpha) {
    int t = blockIdx.x * blockDim.x + threadIdx.x;
    if (t >= EE * HH) return;
    int e = t >> 3, h = t & 7;
    int dst = eidx[EE + e];
    alpha[t] = ex[t] / (ssum[dst * HH + h] + 1e-16f);
}

__global__ void attn_msg(const float* __restrict__ v, const float* __restrict__ ekat,
                         const float* __restrict__ alpha, const float* __restrict__ sw,
                         const int* __restrict__ eidx, const int* __restrict__ pai,
                         float* __restrict__ hout) {
    long long t = (long long)blockIdx.x * blockDim.x + threadIdx.x;
    if (t >= (long long)EE * DD) return;
    int e = (int)(t >> 7), d = (int)(t & 127);
    int h = d >> 4;
    int src = eidx[e], dst = eidx[EE + e], pa = pai[e];
    float m = (v[(size_t)src * DD + d] + ekat[(size_t)pa * DD + d]) *
              alpha[e * HH + h] * sw[t];
    atomicAdd(&hout[(size_t)dst * DD + d], m);
}

__global__ void count_nodes(const int* __restrict__ batch, float* __restrict__ cnt) {
    int n = blockIdx.x * blockDim.x + threadIdx.x;
    if (n >= NN) return;
    atomicAdd(&cnt[batch[n]], 1.f);
}

__global__ void gn_sum(const float* __restrict__ hbuf, const int* __restrict__ batch,
                       float* __restrict__ gsum) {
    int idx = blockIdx.x * blockDim.x + threadIdx.x;
    int warp = idx >> 5, lane = idx & 31;
    if (warp >= NN) return;
    float4 v = ((const float4*)(hbuf + (size_t)warp * DD))[lane];
    float s = v.x + v.y + v.z + v.w;
#pragma unroll
    for (int o = 16; o; o >>= 1) s += __shfl_xor_sync(0xffffffffu, s, o);
    if (!lane) atomicAdd(&gsum[batch[warp]], s);
}

__global__ void gn_var(const float* __restrict__ hbuf, const int* __restrict__ batch,
                       const float* __restrict__ gsum, const float* __restrict__ gcnt,
                       float* __restrict__ gvar) {
    int idx = blockIdx.x * blockDim.x + threadIdx.x;
    int warp = idx >> 5, lane = idx & 31;
    if (warp >= NN) return;
    int g = batch[warp];
    float mean = gsum[g] / (gcnt[g] * DD);
    float4 v = ((const float4*)(hbuf + (size_t)warp * DD))[lane];
    float a = v.x - mean, b = v.y - mean, c = v.z - mean, d = v.w - mean;
    float s = a * a + b * b + c * c + d * d;
#pragma unroll
    for (int o = 16; o; o >>= 1) s += __shfl_xor_sync(0xffffffffu, s, o);
    if (!lane) atomicAdd(&gvar[g], s);
}

__global__ void gn_apply(float* __restrict__ hbuf, const int* __restrict__ batch,
                         const float* __restrict__ gsum, const float* __restrict__ gvar,
                         const float* __restrict__ gcnt) {
    int t = blockIdx.x * blockDim.x + threadIdx.x;
    if (t >= NN * DD) return;
    int n = t >> 7;
    int g = batch[n];
    float inv = 1.f / (gcnt[g] * DD);
    float mean = gsum[g] * inv;
    float var = gvar[g] * inv;
    hbuf[t] = (hbuf[t] - mean) * rsqrtf(var + 1e-8f);
}

__global__ void read_dot(const float* __restrict__ a, const float* __restrict__ w3,
                         const float* __restrict__ b3, float* __restrict__ results) {
    int idx = blockIdx.x * blockDim.x + threadIdx.x;
    int warp = idx >> 5, lane = idx & 31;
    if (warp >= AA) return;
    float4 av = ((const float4*)(a + (size_t)warp * DD))[lane];
    float4 wv = ((const float4*)w3)[lane];
    float s = av.x * wv.x + av.y * wv.y + av.z * wv.z + av.w * wv.w;
#pragma unroll
    for (int o = 16; o; o >>= 1) s += __shfl_xor_sync(0xffffffffu, s, o);
    if (!lane) results[warp] += s + b3[0];
}

__global__ void final_scatter(const float* __restrict__ results, const int* __restrict__ abatch,
                              float* __restrict__ out) {
    int a = blockIdx.x * blockDim.x + threadIdx.x;
    if (a >= AA) return;
    atomicAdd(&out[abatch[a]], results[a] * (1.0f / (float)LL));
}

// ---------------- host orchestration ----------------
static void launch_gemm(const float* A, const float* W, const float* bias,
                        const float* res, const float* mul, float* C,
                        int M, int K, int Nn, int flags) {
    dim3 grid((Nn + BN - 1) / BN, (M + BM - 1) / BM);
    gemm_ep<<<grid, 256>>>(A, W, bias, res, mul, C, M, K, Nn, flags);
}

extern "C" void kernel_launch(void* const* d_in, const int* in_sizes, int n_in,
                              void* d_out, int out_size) {
    const float* x         = (const float*)d_in[0];
    const float* node_rbf  = (const float*)d_in[1];
    const float* edge_sbf  = (const float*)d_in[2];
    const int*   eidx      = (const int*)d_in[3];
    const int*   pai       = (const int*)d_in[4];
    const int*   idx0      = (const int*)d_in[5];
    const int*   abatch    = (const int*)d_in[6];
    const int*   nbatch    = (const int*)d_in[7];
    const float* edgenn_w1 = (const float*)d_in[8];
    const float* edgenn_b1 = (const float*)d_in[9];
    const float* edgenn_w2 = (const float*)d_in[10];
    const float* edgenn_b2 = (const float*)d_in[11];
    const float* conv_wq   = (const float*)d_in[12];
    const float* conv_wk   = (const float*)d_in[13];
    const float* conv_wv   = (const float*)d_in[14];
    const float* conv_we   = (const float*)d_in[15];
    const float* conv_wsbf = (const float*)d_in[16];
    const float* conv_bsbf = (const float*)d_in[17];
    const float* conv_wrbf = (const float*)d_in[18];
    const float* dense_w   = (const float*)d_in[19];
    const float* dense_b   = (const float*)d_in[20];
    const float* bf_w      = (const float*)d_in[21];
    const float* bf_b      = (const float*)d_in[22];
    const float* af_w      = (const float*)d_in[23];
    const float* af_b      = (const float*)d_in[24];
    const float* read_wrbf = (const float*)d_in[25];
    const float* read_w1   = (const float*)d_in[26];
    const float* read_b1   = (const float*)d_in[27];
    const float* read_w2   = (const float*)d_in[28];
    const float* read_b2   = (const float*)d_in[29];
    const float* read_w3   = (const float*)d_in[30];
    const float* read_b3   = (const float*)d_in[31];

    float *featA, *featB, *featC, *featD, *featE, *sw, *ex, *alpha, *ssum;
    float *at1, *at2, *at3, *results, *gsum, *gvar, *gcnt;
    unsigned* menc;
    cudaGetSymbolAddress((void**)&featA, g_featA);
    cudaGetSymbolAddress((void**)&featB, g_featB);
    cudaGetSymbolAddress((void**)&featC, g_featC);
    cudaGetSymbolAddress((void**)&featD, g_featD);
    cudaGetSymbolAddress((void**)&featE, g_featE);
    cudaGetSymbolAddress((void**)&sw, g_sw);
    cudaGetSymbolAddress((void**)&ex, g_ex);
    cudaGetSymbolAddress((void**)&alpha, g_alpha);
    cudaGetSymbolAddress((void**)&menc, g_menc);
    cudaGetSymbolAddress((void**)&ssum, g_ssum);
    cudaGetSymbolAddress((void**)&at1, g_at1);
    cudaGetSymbolAddress((void**)&at2, g_at2);
    cudaGetSymbolAddress((void**)&at3, g_at3);
    cudaGetSymbolAddress((void**)&results, g_results);
    cudaGetSymbolAddress((void**)&gsum, g_gsum);
    cudaGetSymbolAddress((void**)&gvar, g_gvar);
    cudaGetSymbolAddress((void**)&gcnt, g_gcnt);

    cudaMemsetAsync(results, 0, AA * sizeof(float));
    cudaMemsetAsync(gcnt, 0, GG * sizeof(float));
    cudaMemsetAsync(d_out, 0, GG * sizeof(float));
    count_nodes<<<(NN + 255) / 256, 256>>>(nbatch, gcnt);

    // readout helper
    auto readout = [&](int i, const float* cur) {
        // g = cur * (node_rbf @ read_wrbf[i])
        launch_gemm(node_rbf, read_wrbf + (size_t)i * RBFD * DD, nullptr, nullptr, cur,
                    featD, NN, RBFD, DD, EP_MUL);
        cudaMemsetAsync(at1, 0, (size_t)AA * DD * sizeof(float));
        scatter_rows<<<(NN * DD + 255) / 256, 256>>>(featD, idx0, at1, NN);
        launch_gemm(at1, read_w1 + (size_t)i * DD * DD, read_b1 + (size_t)i * DD,
                    nullptr, nullptr, at2, AA, DD, DD, EP_SILU);
        launch_gemm(at2, read_w2 + (size_t)i * DD * DD, read_b2 + (size_t)i * DD,
                    nullptr, nullptr, at3, AA, DD, DD, EP_SILU);
        read_dot<<<(AA * 32 + 255) / 256, 256>>>(at3, read_w3 + (size_t)i * DD,
                                                 read_b3 + i, results);
    };

    const float* cur = x;
    readout(0, cur);

    for (int i = 0; i < LL; i++) {
        size_t dd = (size_t)i * DD * DD;
        // atoms_rep = segsum(cur, idx0, A)
        cudaMemsetAsync(at1, 0, (size_t)AA * DD * sizeof(float));
        scatter_rows<<<(NN * DD + 255) / 256, 256>>>(cur, idx0, at1, NN);
        // edge-NN applied on atoms (commutes with the per-edge gather), then conv_we
        launch_gemm(at1, edgenn_w1 + dd, edgenn_b1 + (size_t)i * DD, nullptr, nullptr,
                    at2, AA, DD, DD, EP_SILU);
        launch_gemm(at2, edgenn_w2 + dd, edgenn_b2 + (size_t)i * DD, nullptr, nullptr,
                    at3, AA, DD, DD, 0);
        launch_gemm(at3, conv_we + dd, nullptr, nullptr, nullptr, at2, AA, DD, DD, 0);
        // q,k,v
        launch_gemm(cur, conv_wq + dd, nullptr, nullptr, nullptr, featB, NN, DD, DD, 0);
        launch_gemm(cur, conv_wk + dd, nullptr, nullptr, nullptr, featC, NN, DD, DD, 0);
        launch_gemm(cur, conv_wv + dd, nullptr, nullptr, nullptr, featD, NN, DD, DD, 0);
        // sbf modulation weights
        launch_gemm(edge_sbf, conv_wsbf + (size_t)i * SBFD * DD, conv_bsbf + (size_t)i * DD,
                    nullptr, nullptr, sw, EE, SBFD, DD, 0);
        // attention softmax over dst segments
        cudaMemsetAsync(menc, 0, NN * HH * sizeof(unsigned));
        cudaMemsetAsync(ssum, 0, NN * HH * sizeof(float));
        attn_logit<<<(EE * HH + 255) / 256, 256>>>(featB, featC, at2, eidx, pai, ex, menc);
        attn_exp<<<(EE * HH + 255) / 256, 256>>>(ex, eidx, menc, ssum);
        attn_alpha<<<(EE * HH + 255) / 256, 256>>>(ex, eidx, ssum, alpha);
        // messages
        cudaMemsetAsync(featE, 0, (size_t)NN * DD * sizeof(float));
        {
            long long tot = (long long)EE * DD;
            attn_msg<<<(unsigned)((tot + 255) / 256), 256>>>(featD, at2, alpha, sw,
                                                             eidx, pai, featE);
        }
        // out = h * (node_rbf @ conv_wrbf[i])
        launch_gemm(node_rbf, conv_wrbf + (size_t)i * RBFD * DD, nullptr, nullptr, featE,
                    featB, NN, RBFD, DD, EP_MUL);
        // graph norm (two-pass, matches reference)
        cudaMemsetAsync(gsum, 0, GG * sizeof(float));
        cudaMemsetAsync(gvar, 0, GG * sizeof(float));
        gn_sum<<<(NN * 32 + 255) / 256, 256>>>(featB, nbatch, gsum);
        gn_var<<<(NN * 32 + 255) / 256, 256>>>(featB, nbatch, gsum, gcnt, gvar);
        gn_apply<<<(NN * DD + 255) / 256, 256>>>(featB, nbatch, gsum, gvar, gcnt);
        // bf residual block
        launch_gemm(featB, bf_w + (size_t)(i * 2 + 0) * DD * DD, bf_b + (size_t)(i * 2 + 0) * DD,
                    nullptr, nullptr, featC, NN, DD, DD, EP_SILU);
        launch_gemm(featC, bf_w + (size_t)(i * 2 + 1) * DD * DD, bf_b + (size_t)(i * 2 + 1) * DD,
                    featB, nullptr, featB, NN, DD, DD, EP_SILU | EP_RES);
        // dense + residual with layer input (res0)
        launch_gemm(featB, dense_w + dd, dense_b + (size_t)i * DD, cur, nullptr,
                    featC, NN, DD, DD, EP_SILU | EP_RES);
        // af residual blocks x2
        launch_gemm(featC, af_w + (size_t)(i * 4 + 0) * DD * DD, af_b + (size_t)(i * 4 + 0) * DD,
                    nullptr, nullptr, featB, NN, DD, DD, EP_SILU);
        launch_gemm(featB, af_w + (size_t)(i * 4 + 1) * DD * DD, af_b + (size_t)(i * 4 + 1) * DD,
                    featC, nullptr, featC, NN, DD, DD, EP_SILU | EP_RES);
        launch_gemm(featC, af_w + (size_t)(i * 4 + 2) * DD * DD, af_b + (size_t)(i * 4 + 2) * DD,
                    nullptr, nullptr, featB, NN, DD, DD, EP_SILU);
        launch_gemm(featB, af_w + (size_t)(i * 4 + 3) * DD * DD, af_b + (size_t)(i * 4 + 3) * DD,
                    featC, nullptr, featC, NN, DD, DD, EP_SILU | EP_RES);
        // readout of new features
        readout(i + 1, featC);
        // rotate for next layer
        if (i < LL - 1) {
            cudaMemcpyAsync(featA, featC, (size_t)NN * DD * sizeof(float),
                            cudaMemcpyDeviceToDevice);
            cur = featA;
        }
    }

    final_scatter<<<(AA + 255) / 256, 256>>>(results, abatch, (float*)d_out);
}

// round 3
// speedup vs baseline: 1.3913x; 1.3913x over previous
#include <cuda_runtime.h>
#include <math.h>
#include <stdint.h>

#define NN 60000
#define EE 300000
#define AA 8000
#define GG 256
#define DD 128
#define HH 8
#define CC 16
#define LL 3
#define RBFD 16
#define SBFD 112

// ---------------- scratch (static device globals; no allocation) ----------------
__device__ float g_featA[NN * DD];
__device__ float g_featB[NN * DD];
__device__ float g_featC[NN * DD];
__device__ float g_featD[NN * DD];
__device__ float g_featE[NN * DD];
__device__ float g_sw[(size_t)EE * DD];
__device__ float g_ex[EE * HH];
__device__ unsigned g_menc[NN * HH];
__device__ float g_ssum[NN * HH];
__device__ float g_at1[AA * DD];
__device__ float g_at2[AA * DD];
__device__ float g_at3[AA * DD];
__device__ float g_results[AA];
__device__ float g_gsum[GG];
__device__ float g_gvar[GG];
__device__ float g_gcnt[GG];

// ---------------- helpers ----------------
__device__ __forceinline__ unsigned fenc(float f) {
    unsigned u = __float_as_uint(f);
    return (u & 0x80000000u) ? ~u : (u | 0x80000000u);
}
__device__ __forceinline__ float fdec(unsigned u) {
    return (u & 0x80000000u) ? __uint_as_float(u ^ 0x80000000u) : __uint_as_float(~u);
}
__device__ __forceinline__ float silu_f(float v) { return v / (1.f + expf(-v)); }

// pack two floats into bf16x2 (x -> low half = first k element, y -> high half)
__device__ __forceinline__ uint32_t pack_bf(float x, float y) {
    uint32_t r;
    asm("cvt.rn.bf16x2.f32 %0, %1, %2;" : "=r"(r) : "f"(y), "f"(x));
    return r;
}
__device__ __forceinline__ float bf_lo(uint32_t u) { return __uint_as_float(u << 16); }
__device__ __forceinline__ float bf_hi(uint32_t u) { return __uint_as_float(u & 0xffff0000u); }

// convert 8 consecutive floats into 4 bf16x2 hi words + 4 lo words
__device__ __forceinline__ void cvt8(const float* f, uint4& hi, uint4& lo) {
    uint32_t h[4], l[4];
#pragma unroll
    for (int p = 0; p < 4; p++) {
        h[p] = pack_bf(f[2 * p], f[2 * p + 1]);
        l[p] = pack_bf(f[2 * p] - bf_lo(h[p]), f[2 * p + 1] - bf_hi(h[p]));
    }
    hi = make_uint4(h[0], h[1], h[2], h[3]);
    lo = make_uint4(l[0], l[1], l[2], l[3]);
}

__device__ __forceinline__ void mma_bf16(float* acc, const uint32_t* a, const uint32_t* b) {
    asm volatile(
        "mma.sync.aligned.m16n8k16.row.col.f32.bf16.bf16.f32 "
        "{%0,%1,%2,%3}, {%4,%5,%6,%7}, {%8,%9}, {%0,%1,%2,%3};\n"
        : "+f"(acc[0]), "+f"(acc[1]), "+f"(acc[2]), "+f"(acc[3])
        : "r"(a[0]), "r"(a[1]), "r"(a[2]), "r"(a[3]), "r"(b[0]), "r"(b[1]));
}

#define EP_SILU 1
#define EP_RES 2
#define EP_MUL 4

// ---------------- bf16x3 split-precision tensor-core GEMM, N fixed = 128 ----------------
// C[M,128] = ep(A[M,K] @ W[K,128] + bias). K multiple of 16.
// Block 128x128, BK=16 double-buffered. 8 warps = 2(M) x 4(N), warp tile 64x32.
// Each operand stored as bf16 hi + bf16 lo; product = hi*hi + hi*lo + lo*hi.
// smem layout [row/n][kpair] with stride 12 words: frag LDS (g,tig) pattern is
// conflict-free (12*g mod 32 = 4*(3g mod 8), a permutation of 4-multiples).
#define SSTR 12

__global__ __launch_bounds__(256) void gemm_bf3(
    const float* __restrict__ A, const float* __restrict__ W,
    const float* __restrict__ bias, const float* __restrict__ res,
    const float* __restrict__ mul, float* __restrict__ C,
    int M, int K, int flags)
{
    __shared__ uint32_t AsH[2][128][SSTR];
    __shared__ uint32_t AsL[2][128][SSTR];
    __shared__ uint32_t WsH[2][128][SSTR];
    __shared__ uint32_t WsL[2][128][SSTR];

    const int tid = threadIdx.x;
    const int wid = tid >> 5, lane = tid & 31;
    const int g = lane >> 2, tig = lane & 3;
    const int m0 = (wid & 1) * 64, n0 = (wid >> 1) * 32;
    const int row0 = blockIdx.x * 128;

    // A staging: 128 rows x 16 k; thread -> (row = tid>>1, 8 floats at (tid&1)*8)
    const int arow = tid >> 1, akf = (tid & 1) * 8, akp = (tid & 1) * 4;
    // W staging: thread -> col n = tid&127, 4 kpairs at jb = (tid>>7)*4
    const int wn = tid & 127, wjb = (tid >> 7) * 4;

    float acc[4][4][4];
#pragma unroll
    for (int mi = 0; mi < 4; mi++)
#pragma unroll
        for (int ni = 0; ni < 4; ni++)
#pragma unroll
            for (int r = 0; r < 4; r++) acc[mi][ni][r] = 0.f;

    const int nc = K >> 4;
    const bool arow_ok = (row0 + arow) < M;
    const float* aptr = A + (size_t)(row0 + arow) * K + akf;

    float fa[8], fw[8];
    // ---- stage chunk 0 ----
    if (arow_ok) {
        *(float4*)&fa[0] = *(const float4*)aptr;
        *(float4*)&fa[4] = *(const float4*)(aptr + 4);
    } else {
#pragma unroll
        for (int p = 0; p < 8; p++) fa[p] = 0.f;
    }
#pragma unroll
    for (int jj = 0; jj < 4; jj++) {
        int k0 = 2 * (wjb + jj);
        fw[2 * jj]     = W[(size_t)k0 * 128 + wn];
        fw[2 * jj + 1] = W[(size_t)(k0 + 1) * 128 + wn];
    }
    {
        uint4 hi, lo;
        cvt8(fa, hi, lo);
        *(uint4*)&AsH[0][arow][akp] = hi;
        *(uint4*)&AsL[0][arow][akp] = lo;
        cvt8(fw, hi, lo);
        *(uint4*)&WsH[0][wn][wjb] = hi;
        *(uint4*)&WsL[0][wn][wjb] = lo;
    }
    __syncthreads();

    int cur = 0;
    for (int c = 0; c < nc; c++) {
        const bool pf = (c + 1 < nc);
        if (pf) {
            const float* ap = aptr + (size_t)(c + 1) * 16;
            if (arow_ok) {
                *(float4*)&fa[0] = *(const float4*)ap;
                *(float4*)&fa[4] = *(const float4*)(ap + 4);
            } else {
#pragma unroll
                for (int p = 0; p < 8; p++) fa[p] = 0.f;
            }
            const float* wp = W + (size_t)(c + 1) * 16 * 128;
#pragma unroll
            for (int jj = 0; jj < 4; jj++) {
                int k0 = 2 * (wjb + jj);
                fw[2 * jj]     = wp[(size_t)k0 * 128 + wn];
                fw[2 * jj + 1] = wp[(size_t)(k0 + 1) * 128 + wn];
            }
        }
        // ---- compute chunk `cur` ----
        uint32_t bH[4][2], bL[4][2];
#pragma unroll
        for (int ni = 0; ni < 4; ni++) {
            int n = n0 + ni * 8 + g;
            bH[ni][0] = WsH[cur][n][tig];
            bH[ni][1] = WsH[cur][n][tig + 4];
            bL[ni][0] = WsL[cur][n][tig];
            bL[ni][1] = WsL[cur][n][tig + 4];
        }
#pragma unroll
        for (int mi = 0; mi < 4; mi++) {
            int m = m0 + mi * 16 + g;
            uint32_t aH[4], aL[4];
            aH[0] = AsH[cur][m][tig];     aH[1] = AsH[cur][m + 8][tig];
            aH[2] = AsH[cur][m][tig + 4]; aH[3] = AsH[cur][m + 8][tig + 4];
            aL[0] = AsL[cur][m][tig];     aL[1] = AsL[cur][m + 8][tig];
            aL[2] = AsL[cur][m][tig + 4]; aL[3] = AsL[cur][m + 8][tig + 4];
#pragma unroll
            for (int ni = 0; ni < 4; ni++) {
                mma_bf16(acc[mi][ni], aH, bH[ni]);
                mma_bf16(acc[mi][ni], aH, bL[ni]);
                mma_bf16(acc[mi][ni], aL, bH[ni]);
            }
        }
        if (pf) {
            int nb = cur ^ 1;
            uint4 hi, lo;
            cvt8(fa, hi, lo);
            *(uint4*)&AsH[nb][arow][akp] = hi;
            *(uint4*)&AsL[nb][arow][akp] = lo;
            cvt8(fw, hi, lo);
            *(uint4*)&WsH[nb][wn][wjb] = hi;
            *(uint4*)&WsL[nb][wn][wjb] = lo;
        }
        __syncthreads();
        cur ^= 1;
    }

    // ---- epilogue (m16n8 acc layout: rows g/g+8, cols 2*tig, 2*tig+1) ----
#pragma unroll
    for (int mi = 0; mi < 4; mi++) {
        int rbase = row0 + m0 + mi * 16 + g;
#pragma unroll
        for (int ni = 0; ni < 4; ni++) {
            int cidx = n0 + ni * 8 + tig * 2;
#pragma unroll
            for (int half = 0; half < 2; half++) {
                int r = rbase + half * 8;
                if (r >= M) continue;
                float vx = acc[mi][ni][half * 2 + 0];
                float vy = acc[mi][ni][half * 2 + 1];
                if (bias) { vx += bias[cidx]; vy += bias[cidx + 1]; }
                if (flags & EP_SILU) { vx = silu_f(vx); vy = silu_f(vy); }
                size_t off = (size_t)r * 128 + cidx;
                if (flags & EP_RES) {
                    float2 rr = *(const float2*)(res + off);
                    vx += rr.x; vy += rr.y;
                }
                if (flags & EP_MUL) {
                    float2 mm = *(const float2*)(mul + off);
                    vx *= mm.x; vy *= mm.y;
                }
                *(float2*)(C + off) = make_float2(vx, vy);
            }
        }
    }
}

// ---------------- scatter / attention / norm kernels ----------------
__global__ void scatter_rows(const float* __restrict__ src, const int* __restrict__ idx,
                             float* __restrict__ dst, int rows) {
    int t = blockIdx.x * blockDim.x + threadIdx.x;
    if (t >= rows * DD) return;
    int n = t >> 7, d = t & 127;
    atomicAdd(&dst[(size_t)idx[n] * DD + d], src[t]);
}

__global__ void attn_logit(const float* __restrict__ q, const float* __restrict__ k,
                           const float* __restrict__ ekat, const int* __restrict__ eidx,
                           const int* __restrict__ pai, float* __restrict__ logit,
                           unsigned* __restrict__ menc) {
    int t = blockIdx.x * blockDim.x + threadIdx.x;
    if (t >= EE * HH) return;
    int e = t >> 3, h = t & 7;
    int src = eidx[e], dst = eidx[EE + e], pa = pai[e];
    const float4* qp = (const float4*)(q + (size_t)dst * DD + h * CC);
    const float4* kp = (const float4*)(k + (size_t)src * DD + h * CC);
    const float4* ep = (const float4*)(ekat + (size_t)pa * DD + h * CC);
    float s = 0.f;
#pragma unroll
    for (int i = 0; i < 4; i++) {
        float4 a = qp[i], b = kp[i], c = ep[i];
        s += a.x * (b.x + c.x) + a.y * (b.y + c.y) + a.z * (b.z + c.z) + a.w * (b.w + c.w);
    }
    s *= 0.25f;  // 1/sqrt(C), C=16
    logit[t] = s;
    atomicMax(&menc[dst * HH + h], fenc(s));
}

__global__ void attn_exp(float* __restrict__ ex, const int* __restrict__ eidx,
                         const unsigned* __restrict__ menc, float* __restrict__ ssum) {
    int t = blockIdx.x * blockDim.x + threadIdx.x;
    if (t >= EE * HH) return;
    int e = t >> 3, h = t & 7;
    int dst = eidx[EE + e];
    float mm = fdec(menc[dst * HH + h]);
    float v = expf(ex[t] - mm);
    ex[t] = v;
    atomicAdd(&ssum[dst * HH + h], v);
}

__global__ void attn_msg(const float* __restrict__ v, const float* __restrict__ ekat,
                         const float* __restrict__ ex, const float* __restrict__ ssum,
                         const float* __restrict__ sw,
                         const int* __restrict__ eidx, const int* __restrict__ pai,
                         float* __restrict__ hout) {
    long long t = (long long)blockIdx.x * blockDim.x + threadIdx.x;
    if (t >= (long long)EE * DD) return;
    int e = (int)(t >> 7), d = (int)(t & 127);
    int h = d >> 4;
    int src = eidx[e], dst = eidx[EE + e], pa = pai[e];
    float al = ex[e * HH + h] / (ssum[dst * HH + h] + 1e-16f);
    float m = (v[(size_t)src * DD + d] + ekat[(size_t)pa * DD + d]) * al * sw[t];
    atomicAdd(&hout[(size_t)dst * DD + d], m);
}

__global__ void count_nodes(const int* __restrict__ batch, float* __restrict__ cnt) {
    int n = blockIdx.x * blockDim.x + threadIdx.x;
    if (n >= NN) return;
    atomicAdd(&cnt[batch[n]], 1.f);
}

__global__ void gn_sum(const float* __restrict__ hbuf, const int* __restrict__ batch,
                       float* __restrict__ gsum) {
    int idx = blockIdx.x * blockDim.x + threadIdx.x;
    int warp = idx >> 5, lane = idx & 31;
    if (warp >= NN) return;
    float4 v = ((const float4*)(hbuf + (size_t)warp * DD))[lane];
    float s = v.x + v.y + v.z + v.w;
#pragma unroll
    for (int o = 16; o; o >>= 1) s += __shfl_xor_sync(0xffffffffu, s, o);
    if (!lane) atomicAdd(&gsum[batch[warp]], s);
}

__global__ void gn_var(const float* __restrict__ hbuf, const int* __restrict__ batch,
                       const float* __restrict__ gsum, const float* __restrict__ gcnt,
                       float* __restrict__ gvar) {
    int idx = blockIdx.x * blockDim.x + threadIdx.x;
    int warp = idx >> 5, lane = idx & 31;
    if (warp >= NN) return;
    int g = batch[warp];
    float mean = gsum[g] / (gcnt[g] * DD);
    float4 v = ((const float4*)(hbuf + (size_t)warp * DD))[lane];
    float a = v.x - mean, b = v.y - mean, c = v.z - mean, d = v.w - mean;
    float s = a * a + b * b + c * c + d * d;
#pragma unroll
    for (int o = 16; o; o >>= 1) s += __shfl_xor_sync(0xffffffffu, s, o);
    if (!lane) atomicAdd(&gvar[g], s);
}

__global__ void gn_apply(float* __restrict__ hbuf, const int* __restrict__ batch,
                         const float* __restrict__ gsum, const float* __restrict__ gvar,
                         const float* __restrict__ gcnt) {
    int t = blockIdx.x * blockDim.x + threadIdx.x;
    if (t >= NN * DD) return;
    int n = t >> 7;
    int g = batch[n];
    float inv = 1.f / (gcnt[g] * DD);
    float mean = gsum[g] * inv;
    float var = gvar[g] * inv;
    hbuf[t] = (hbuf[t] - mean) * rsqrtf(var + 1e-8f);
}

__global__ void read_dot(const float* __restrict__ a, const float* __restrict__ w3,
                         const float* __restrict__ b3, float* __restrict__ results) {
    int idx = blockIdx.x * blockDim.x + threadIdx.x;
    int warp = idx >> 5, lane = idx & 31;
    if (warp >= AA) return;
    float4 av = ((const float4*)(a + (size_t)warp * DD))[lane];
    float4 wv = ((const float4*)w3)[lane];
    float s = av.x * wv.x + av.y * wv.y + av.z * wv.z + av.w * wv.w;
#pragma unroll
    for (int o = 16; o; o >>= 1) s += __shfl_xor_sync(0xffffffffu, s, o);
    if (!lane) results[warp] += s + b3[0];
}

__global__ void final_scatter(const float* __restrict__ results, const int* __restrict__ abatch,
                              float* __restrict__ out) {
    int a = blockIdx.x * blockDim.x + threadIdx.x;
    if (a >= AA) return;
    atomicAdd(&out[abatch[a]], results[a] * (1.0f / (float)LL));
}

// ---------------- host orchestration ----------------
static void launch_gemm(const float* A, const float* W, const float* bias,
                        const float* res, const float* mul, float* C,
                        int M, int K, int flags) {
    gemm_bf3<<<(M + 127) / 128, 256>>>(A, W, bias, res, mul, C, M, K, flags);
}

extern "C" void kernel_launch(void* const* d_in, const int* in_sizes, int n_in,
                              void* d_out, int out_size) {
    const float* x         = (const float*)d_in[0];
    const float* node_rbf  = (const float*)d_in[1];
    const float* edge_sbf  = (const float*)d_in[2];
    const int*   eidx      = (const int*)d_in[3];
    const int*   pai       = (const int*)d_in[4];
    const int*   idx0      = (const int*)d_in[5];
    const int*   abatch    = (const int*)d_in[6];
    const int*   nbatch    = (const int*)d_in[7];
    const float* edgenn_w1 = (const float*)d_in[8];
    const float* edgenn_b1 = (const float*)d_in[9];
    const float* edgenn_w2 = (const float*)d_in[10];
    const float* edgenn_b2 = (const float*)d_in[11];
    const float* conv_wq   = (const float*)d_in[12];
    const float* conv_wk   = (const float*)d_in[13];
    const float* conv_wv   = (const float*)d_in[14];
    const float* conv_we   = (const float*)d_in[15];
    const float* conv_wsbf = (const float*)d_in[16];
    const float* conv_bsbf = (const float*)d_in[17];
    const float* conv_wrbf = (const float*)d_in[18];
    const float* dense_w   = (const float*)d_in[19];
    const float* dense_b   = (const float*)d_in[20];
    const float* bf_w      = (const float*)d_in[21];
    const float* bf_b      = (const float*)d_in[22];
    const float* af_w      = (const float*)d_in[23];
    const float* af_b      = (const float*)d_in[24];
    const float* read_wrbf = (const float*)d_in[25];
    const float* read_w1   = (const float*)d_in[26];
    const float* read_b1   = (const float*)d_in[27];
    const float* read_w2   = (const float*)d_in[28];
    const float* read_b2   = (const float*)d_in[29];
    const float* read_w3   = (const float*)d_in[30];
    const float* read_b3   = (const float*)d_in[31];

    float *featA, *featB, *featC, *featD, *featE, *sw, *ex, *ssum;
    float *at1, *at2, *at3, *results, *gsum, *gvar, *gcnt;
    unsigned* menc;
    cudaGetSymbolAddress((void**)&featA, g_featA);
    cudaGetSymbolAddress((void**)&featB, g_featB);
    cudaGetSymbolAddress((void**)&featC, g_featC);
    cudaGetSymbolAddress((void**)&featD, g_featD);
    cudaGetSymbolAddress((void**)&featE, g_featE);
    cudaGetSymbolAddress((void**)&sw, g_sw);
    cudaGetSymbolAddress((void**)&ex, g_ex);
    cudaGetSymbolAddress((void**)&menc, g_menc);
    cudaGetSymbolAddress((void**)&ssum, g_ssum);
    cudaGetSymbolAddress((void**)&at1, g_at1);
    cudaGetSymbolAddress((void**)&at2, g_at2);
    cudaGetSymbolAddress((void**)&at3, g_at3);
    cudaGetSymbolAddress((void**)&results, g_results);
    cudaGetSymbolAddress((void**)&gsum, g_gsum);
    cudaGetSymbolAddress((void**)&gvar, g_gvar);
    cudaGetSymbolAddress((void**)&gcnt, g_gcnt);

    cudaMemsetAsync(results, 0, AA * sizeof(float));
    cudaMemsetAsync(gcnt, 0, GG * sizeof(float));
    cudaMemsetAsync(d_out, 0, GG * sizeof(float));
    count_nodes<<<(NN + 255) / 256, 256>>>(nbatch, gcnt);

    // readout helper — uses featE as the gated temp (v is dead when called)
    auto readout = [&](int i, const float* cur) {
        launch_gemm(node_rbf, read_wrbf + (size_t)i * RBFD * DD, nullptr, nullptr, cur,
                    featE, NN, RBFD, EP_MUL);
        cudaMemsetAsync(at1, 0, (size_t)AA * DD * sizeof(float));
        scatter_rows<<<(NN * DD + 255) / 256, 256>>>(featE, idx0, at1, NN);
        launch_gemm(at1, read_w1 + (size_t)i * DD * DD, read_b1 + (size_t)i * DD,
                    nullptr, nullptr, at2, AA, DD, EP_SILU);
        launch_gemm(at2, read_w2 + (size_t)i * DD * DD, read_b2 + (size_t)i * DD,
                    nullptr, nullptr, at3, AA, DD, EP_SILU);
        read_dot<<<(AA * 32 + 255) / 256, 256>>>(at3, read_w3 + (size_t)i * DD,
                                                 read_b3 + i, results);
    };

    const float* cur = x;
    readout(0, cur);

    for (int i = 0; i < LL; i++) {
        size_t dd = (size_t)i * DD * DD;
        float* kt = (cur == featC) ? featD : featC;  // layer chain temp / output
        // atoms_rep = segsum(cur, idx0, A); edge-NN + conv_we on atoms (commute with gather)
        cudaMemsetAsync(at1, 0, (size_t)AA * DD * sizeof(float));
        scatter_rows<<<(NN * DD + 255) / 256, 256>>>(cur, idx0, at1, NN);
        launch_gemm(at1, edgenn_w1 + dd, edgenn_b1 + (size_t)i * DD, nullptr, nullptr,
                    at2, AA, DD, EP_SILU);
        launch_gemm(at2, edgenn_w2 + dd, edgenn_b2 + (size_t)i * DD, nullptr, nullptr,
                    at3, AA, DD, 0);
        launch_gemm(at3, conv_we + dd, nullptr, nullptr, nullptr, at2, AA, DD, 0);
        // q -> featB, k -> kt, v -> featE
        launch_gemm(cur, conv_wq + dd, nullptr, nullptr, nullptr, featB, NN, DD, 0);
        launch_gemm(cur, conv_wk + dd, nullptr, nullptr, nullptr, kt, NN, DD, 0);
        launch_gemm(cur, conv_wv + dd, nullptr, nullptr, nullptr, featE, NN, DD, 0);
        // sbf modulation weights
        launch_gemm(edge_sbf, conv_wsbf + (size_t)i * SBFD * DD, conv_bsbf + (size_t)i * DD,
                    nullptr, nullptr, sw, EE, SBFD, 0);
        // attention softmax over dst segments
        cudaMemsetAsync(menc, 0, NN * HH * sizeof(unsigned));
        cudaMemsetAsync(ssum, 0, NN * HH * sizeof(float));
        attn_logit<<<(EE * HH + 255) / 256, 256>>>(featB, kt, at2, eidx, pai, ex, menc);
        attn_exp<<<(EE * HH + 255) / 256, 256>>>(ex, eidx, menc, ssum);
        // messages (alpha fused) -> featA
        cudaMemsetAsync(featA, 0, (size_t)NN * DD * sizeof(float));
        {
            long long tot = (long long)EE * DD;
            attn_msg<<<(unsigned)((tot + 255) / 256), 256>>>(featE, at2, ex, ssum, sw,
                                                             eidx, pai, featA);
        }
        // out = msg * (node_rbf @ conv_wrbf[i]) -> featB (q dead)
        launch_gemm(node_rbf, conv_wrbf + (size_t)i * RBFD * DD, nullptr, nullptr, featA,
                    featB, NN, RBFD, EP_MUL);
        // graph norm in place on featB
        cudaMemsetAsync(gsum, 0, GG * sizeof(float));
        cudaMemsetAsync(gvar, 0, GG * sizeof(float));
        gn_sum<<<(NN * 32 + 255) / 256, 256>>>(featB, nbatch, gsum);
        gn_var<<<(NN * 32 + 255) / 256, 256>>>(featB, nbatch, gsum, gcnt, gvar);
        gn_apply<<<(NN * DD + 255) / 256, 256>>>(featB, nbatch, gsum, gvar, gcnt);
        // bf residual block: featB -> kt -> featB (in-place residual)
        launch_gemm(featB, bf_w + (size_t)(i * 2 + 0) * DD * DD, bf_b + (size_t)(i * 2 + 0) * DD,
                    nullptr, nullptr, kt, NN, DD, EP_SILU);
        launch_gemm(kt, bf_w + (size_t)(i * 2 + 1) * DD * DD, bf_b + (size_t)(i * 2 + 1) * DD,
                    featB, nullptr, featB, NN, DD, EP_SILU | EP_RES);
        // dense + residual with layer input (res0 = cur) -> kt
        launch_gemm(featB, dense_w + dd, dense_b + (size_t)i * DD, cur, nullptr,
                    kt, NN, DD, EP_SILU | EP_RES);
        // af residual blocks x2: kt <-> featB, ending in kt
        launch_gemm(kt, af_w + (size_t)(i * 4 + 0) * DD * DD, af_b + (size_t)(i * 4 + 0) * DD,
                    nullptr, nullptr, featB, NN, DD, EP_SILU);
        launch_gemm(featB, af_w + (size_t)(i * 4 + 1) * DD * DD, af_b + (size_t)(i * 4 + 1) * DD,
                    kt, nullptr, kt, NN, DD, EP_SILU | EP_RES);
        launch_gemm(kt, af_w + (size_t)(i * 4 + 2) * DD * DD, af_b + (size_t)(i * 4 + 2) * DD,
                    nullptr, nullptr, featB, NN, DD, EP_SILU);
        launch_gemm(featB, af_w + (size_t)(i * 4 + 3) * DD * DD, af_b + (size_t)(i * 4 + 3) * DD,
                    kt, nullptr, kt, NN, DD, EP_SILU | EP_RES);
        // readout of new features
        readout(i + 1, kt);
        cur = kt;  // ping-pong, no memcpy
    }

    final_scatter<<<(AA + 255) / 256, 256>>>(results, abatch, (float*)d_out);
}

// round 4
// speedup vs baseline: 1.4671x; 1.0545x over previous
#include <cuda_runtime.h>
#include <math.h>
#include <stdint.h>

#define NN 60000
#define EE 300000
#define AA 8000
#define GG 256
#define DD 128
#define HH 8
#define CC 16
#define LL 3
#define RBFD 16
#define SBFD 112

// ---------------- scratch (static device globals; no allocation) ----------------
__device__ float g_featA[NN * DD];
__device__ float g_featB[NN * DD];
__device__ float g_featC[NN * DD];
__device__ float g_featD[NN * DD];
__device__ float g_featE[NN * DD];
__device__ float g_sw[(size_t)EE * DD];
__device__ float g_at1[AA * DD];
__device__ float g_at2[AA * DD];
__device__ float g_at3[AA * DD];
__device__ float g_results[AA];
__device__ float g_gsum[GG];
__device__ float g_gvar[GG];
__device__ float g_gcnt[GG];
// CSR scratch (indices are constant per call; built once, reused)
__device__ int g_eoff[NN + 1];
__device__ int g_epos[NN];
__device__ int g_ecsr[EE];
__device__ int g_aoff[AA + 1];
__device__ int g_apos[AA];
__device__ int g_acsr[NN];

// ---------------- helpers ----------------
__device__ __forceinline__ float silu_f(float v) { return v / (1.f + expf(-v)); }

// pack two floats into bf16x2 (x -> low half = first k element, y -> high half)
__device__ __forceinline__ uint32_t pack_bf(float x, float y) {
    uint32_t r;
    asm("cvt.rn.bf16x2.f32 %0, %1, %2;" : "=r"(r) : "f"(y), "f"(x));
    return r;
}
__device__ __forceinline__ float bf_lo(uint32_t u) { return __uint_as_float(u << 16); }
__device__ __forceinline__ float bf_hi(uint32_t u) { return __uint_as_float(u & 0xffff0000u); }

__device__ __forceinline__ void mma_bf16(float* acc, const uint32_t* a, const uint32_t* b) {
    asm volatile(
        "mma.sync.aligned.m16n8k16.row.col.f32.bf16.bf16.f32 "
        "{%0,%1,%2,%3}, {%4,%5,%6,%7}, {%8,%9}, {%0,%1,%2,%3};\n"
        : "+f"(acc[0]), "+f"(acc[1]), "+f"(acc[2]), "+f"(acc[3])
        : "r"(a[0]), "r"(a[1]), "r"(a[2]), "r"(a[3]), "r"(b[0]), "r"(b[1]));
}

#define EP_SILU 1
#define EP_RES 2
#define EP_MUL 4

// ---------------- bf16x3 split-precision tensor-core GEMM, N fixed = 128 ----------------
// C[M,128] = ep(A[M,K] @ W[K,128] + bias). K multiple of 16.
// Block 128x128, BK=16 double-buffered, 512 threads = 16 warps (4M x 4N),
// warp tile 32x32 (2 m16 x 4 n8), product = hi*hi + hi*lo + lo*hi.
// smem stride 12 words: frag LDS (g,tig) pattern covers all 32 banks.
#define SSTR 12

__global__ __launch_bounds__(512) void gemm_bf3(
    const float* __restrict__ A, const float* __restrict__ W,
    const float* __restrict__ bias, const float* __restrict__ res,
    const float* __restrict__ mul, float* __restrict__ C,
    int M, int K, int flags)
{
    __shared__ uint32_t AsH[2][128][SSTR];
    __shared__ uint32_t AsL[2][128][SSTR];
    __shared__ uint32_t WsH[2][128][SSTR];
    __shared__ uint32_t WsL[2][128][SSTR];

    const int tid = threadIdx.x;
    const int wid = tid >> 5, lane = tid & 31;
    const int g = lane >> 2, tig = lane & 3;
    const int m0 = (wid & 3) * 32, n0 = (wid >> 2) * 32;
    const int row0 = blockIdx.x * 128;

    // A staging: thread -> row tid>>2, 4 floats at (tid&3)*4
    const int arow = tid >> 2, akf = (tid & 3) * 4, akp = (tid & 3) * 2;
    // W staging: thread -> col tid&127, 4 k's at (tid>>7)*4
    const int wn = tid & 127, wkb = (tid >> 7) * 4, wkp = (tid >> 7) * 2;

    float acc[2][4][4];
#pragma unroll
    for (int mi = 0; mi < 2; mi++)
#pragma unroll
        for (int ni = 0; ni < 4; ni++)
#pragma unroll
            for (int r = 0; r < 4; r++) acc[mi][ni][r] = 0.f;

    const int nc = K >> 4;
    const bool arow_ok = (row0 + arow) < M;
    const float* aptr = A + (size_t)(row0 + arow) * K + akf;

    float4 fa;
    float fw[4];
    // ---- stage chunk 0 ----
    fa = arow_ok ? *(const float4*)aptr : make_float4(0, 0, 0, 0);
#pragma unroll
    for (int j = 0; j < 4; j++) fw[j] = W[(size_t)(wkb + j) * 128 + wn];
    {
        uint32_t h0 = pack_bf(fa.x, fa.y), h1 = pack_bf(fa.z, fa.w);
        AsH[0][arow][akp] = h0; AsH[0][arow][akp + 1] = h1;
        AsL[0][arow][akp]     = pack_bf(fa.x - bf_lo(h0), fa.y - bf_hi(h0));
        AsL[0][arow][akp + 1] = pack_bf(fa.z - bf_lo(h1), fa.w - bf_hi(h1));
        uint32_t w0 = pack_bf(fw[0], fw[1]), w1 = pack_bf(fw[2], fw[3]);
        WsH[0][wn][wkp] = w0; WsH[0][wn][wkp + 1] = w1;
        WsL[0][wn][wkp]     = pack_bf(fw[0] - bf_lo(w0), fw[1] - bf_hi(w0));
        WsL[0][wn][wkp + 1] = pack_bf(fw[2] - bf_lo(w1), fw[3] - bf_hi(w1));
    }
    __syncthreads();

    int cur = 0;
    for (int c = 0; c < nc; c++) {
        const bool pf = (c + 1 < nc);
        if (pf) {
            const float* ap = aptr + (size_t)(c + 1) * 16;
            fa = arow_ok ? *(const float4*)ap : make_float4(0, 0, 0, 0);
            const float* wp = W + (size_t)(c + 1) * 16 * 128;
#pragma unroll
            for (int j = 0; j < 4; j++) fw[j] = wp[(size_t)(wkb + j) * 128 + wn];
        }
        // ---- compute chunk `cur` ----
        uint32_t bH[4][2], bL[4][2];
#pragma unroll
        for (int ni = 0; ni < 4; ni++) {
            int n = n0 + ni * 8 + g;
            bH[ni][0] = WsH[cur][n][tig];
            bH[ni][1] = WsH[cur][n][tig + 4];
            bL[ni][0] = WsL[cur][n][tig];
            bL[ni][1] = WsL[cur][n][tig + 4];
        }
#pragma unroll
        for (int mi = 0; mi < 2; mi++) {
            int m = m0 + mi * 16 + g;
            uint32_t aH[4], aL[4];
            aH[0] = AsH[cur][m][tig];     aH[1] = AsH[cur][m + 8][tig];
            aH[2] = AsH[cur][m][tig + 4]; aH[3] = AsH[cur][m + 8][tig + 4];
            aL[0] = AsL[cur][m][tig];     aL[1] = AsL[cur][m + 8][tig];
            aL[2] = AsL[cur][m][tig + 4]; aL[3] = AsL[cur][m + 8][tig + 4];
#pragma unroll
            for (int ni = 0; ni < 4; ni++) {
                mma_bf16(acc[mi][ni], aH, bH[ni]);
                mma_bf16(acc[mi][ni], aH, bL[ni]);
                mma_bf16(acc[mi][ni], aL, bH[ni]);
            }
        }
        if (pf) {
            int nb = cur ^ 1;
            uint32_t h0 = pack_bf(fa.x, fa.y), h1 = pack_bf(fa.z, fa.w);
            AsH[nb][arow][akp] = h0; AsH[nb][arow][akp + 1] = h1;
            AsL[nb][arow][akp]     = pack_bf(fa.x - bf_lo(h0), fa.y - bf_hi(h0));
            AsL[nb][arow][akp + 1] = pack_bf(fa.z - bf_lo(h1), fa.w - bf_hi(h1));
            uint32_t w0 = pack_bf(fw[0], fw[1]), w1 = pack_bf(fw[2], fw[3]);
            WsH[nb][wn][wkp] = w0; WsH[nb][wn][wkp + 1] = w1;
            WsL[nb][wn][wkp]     = pack_bf(fw[0] - bf_lo(w0), fw[1] - bf_hi(w0));
            WsL[nb][wn][wkp + 1] = pack_bf(fw[2] - bf_lo(w1), fw[3] - bf_hi(w1));
        }
        __syncthreads();
        cur ^= 1;
    }

    // ---- epilogue (acc rows g/g+8, cols 2*tig, 2*tig+1) ----
#pragma unroll
    for (int mi = 0; mi < 2; mi++) {
        int rbase = row0 + m0 + mi * 16 + g;
#pragma unroll
        for (int ni = 0; ni < 4; ni++) {
            int cidx = n0 + ni * 8 + tig * 2;
#pragma unroll
            for (int half = 0; half < 2; half++) {
                int r = rbase + half * 8;
                if (r >= M) continue;
                float vx = acc[mi][ni][half * 2 + 0];
                float vy = acc[mi][ni][half * 2 + 1];
                if (bias) { vx += bias[cidx]; vy += bias[cidx + 1]; }
                if (flags & EP_SILU) { vx = silu_f(vx); vy = silu_f(vy); }
                size_t off = (size_t)r * 128 + cidx;
                if (flags & EP_RES) {
                    float2 rr = *(const float2*)(res + off);
                    vx += rr.x; vy += rr.y;
                }
                if (flags & EP_MUL) {
                    float2 mm = *(const float2*)(mul + off);
                    vx *= mm.x; vy *= mm.y;
                }
                *(float2*)(C + off) = make_float2(vx, vy);
            }
        }
    }
}

// ---------------- CSR construction (built once per call, indices constant) ----------------
__global__ void hist_seg(const int* __restrict__ idx, int n, int* __restrict__ deg) {
    int t = blockIdx.x * blockDim.x + threadIdx.x;
    if (t >= n) return;
    atomicAdd(&deg[idx[t] + 1], 1);
}

// single-block inclusive scan over deg[1..n]; deg[0] must be 0
__global__ void scan_offsets(int* __restrict__ deg, int n) {
    __shared__ int buf[1024];
    __shared__ int carry;
    if (threadIdx.x == 0) carry = 0;
    __syncthreads();
    for (int base = 0; base < n; base += 1024) {
        int i = base + threadIdx.x;
        int v = (i < n) ? deg[i + 1] : 0;
        buf[threadIdx.x] = v;
        __syncthreads();
        for (int off = 1; off < 1024; off <<= 1) {
            int t = (threadIdx.x >= off) ? buf[threadIdx.x - off] : 0;
            __syncthreads();
            buf[threadIdx.x] += t;
            __syncthreads();
        }
        int total = buf[1023];
        if (i < n) deg[i + 1] = buf[threadIdx.x] + carry;
        __syncthreads();
        if (threadIdx.x == 0) carry += total;
        __syncthreads();
    }
}

__global__ void fill_csr(const int* __restrict__ idx, int n, int* __restrict__ pos,
                         int* __restrict__ csr) {
    int t = blockIdx.x * blockDim.x + threadIdx.x;
    if (t >= n) return;
    int p = atomicAdd(&pos[idx[t]], 1);
    csr[p] = t;
}

// ---------------- CSR gather: dst[a,:] = sum over csr segment of src rows ----------------
__global__ void gather_rows_csr(const float* __restrict__ src, const int* __restrict__ off,
                                const int* __restrict__ csr, float* __restrict__ dst, int nseg) {
    int idx = blockIdx.x * blockDim.x + threadIdx.x;
    int w = idx >> 5, lane = idx & 31;
    if (w >= nseg) return;
    int s = off[w], e = off[w + 1];
    float4 acc = make_float4(0, 0, 0, 0);
    for (int j = s; j < e; j++) {
        int n = csr[j];
        float4 v = ((const float4*)(src + (size_t)n * DD))[lane];
        acc.x += v.x; acc.y += v.y; acc.z += v.z; acc.w += v.w;
    }
    ((float4*)(dst + (size_t)w * DD))[lane] = acc;
}

// ---------------- fused CSR attention: warp per dst node, no atomics ----------------
// out[dst,:] = sum_e ex_e*(v[src]+ek[pa])*sw[e] / (sum_e ex_e + 1e-16), per head
__global__ void attn_csr(const float* __restrict__ q, const float* __restrict__ k,
                         const float* __restrict__ v, const float* __restrict__ ek,
                         const float* __restrict__ sw, const int* __restrict__ esrc,
                         const int* __restrict__ pai, const int* __restrict__ off,
                         const int* __restrict__ csr, float* __restrict__ out) {
    int idx = blockIdx.x * blockDim.x + threadIdx.x;
    int w = idx >> 5, lane = idx & 31;
    if (w >= NN) return;
    int s0 = off[w], s1 = off[w + 1];
    float4 q4 = ((const float4*)(q + (size_t)w * DD))[lane];

    // pass 1: per-head max logit
    float mx = -1e30f;
    for (int j = s0; j < s1; j++) {
        int e = csr[j];
        int sn = esrc[e], pa = pai[e];
        float4 k4 = ((const float4*)(k + (size_t)sn * DD))[lane];
        float4 e4 = ((const float4*)(ek + (size_t)pa * DD))[lane];
        float p = q4.x * (k4.x + e4.x) + q4.y * (k4.y + e4.y) +
                  q4.z * (k4.z + e4.z) + q4.w * (k4.w + e4.w);
        p += __shfl_xor_sync(0xffffffffu, p, 1);
        p += __shfl_xor_sync(0xffffffffu, p, 2);
        p *= 0.25f;  // 1/sqrt(16)
        mx = fmaxf(mx, p);
    }

    // pass 2: accumulate numerator and denominator
    float4 acc = make_float4(0, 0, 0, 0);
    float den = 0.f;
    for (int j = s0; j < s1; j++) {
        int e = csr[j];
        int sn = esrc[e], pa = pai[e];
        float4 k4 = ((const float4*)(k + (size_t)sn * DD))[lane];
        float4 e4 = ((const float4*)(ek + (size_t)pa * DD))[lane];
        float p = q4.x * (k4.x + e4.x) + q4.y * (k4.y + e4.y) +
                  q4.z * (k4.z + e4.z) + q4.w * (k4.w + e4.w);
        p += __shfl_xor_sync(0xffffffffu, p, 1);
        p += __shfl_xor_sync(0xffffffffu, p, 2);
        p *= 0.25f;
        float ex = expf(p - mx);
        den += ex;
        float4 v4 = ((const float4*)(v + (size_t)sn * DD))[lane];
        float4 s4 = ((const float4*)(sw + (size_t)e * DD))[lane];
        acc.x += ex * (v4.x + e4.x) * s4.x;
        acc.y += ex * (v4.y + e4.y) * s4.y;
        acc.z += ex * (v4.z + e4.z) * s4.z;
        acc.w += ex * (v4.w + e4.w) * s4.w;
    }
    float inv = 1.f / (den + 1e-16f);
    acc.x *= inv; acc.y *= inv; acc.z *= inv; acc.w *= inv;
    ((float4*)(out + (size_t)w * DD))[lane] = acc;
}

// ---------------- norm / readout kernels ----------------
__global__ void count_nodes(const int* __restrict__ batch, float* __restrict__ cnt) {
    int n = blockIdx.x * blockDim.x + threadIdx.x;
    if (n >= NN) return;
    atomicAdd(&cnt[batch[n]], 1.f);
}

__global__ void gn_sum(const float* __restrict__ hbuf, const int* __restrict__ batch,
                       float* __restrict__ gsum) {
    int idx = blockIdx.x * blockDim.x + threadIdx.x;
    int warp = idx >> 5, lane = idx & 31;
    if (warp >= NN) return;
    float4 v = ((const float4*)(hbuf + (size_t)warp * DD))[lane];
    float s = v.x + v.y + v.z + v.w;
#pragma unroll
    for (int o = 16; o; o >>= 1) s += __shfl_xor_sync(0xffffffffu, s, o);
    if (!lane) atomicAdd(&gsum[batch[warp]], s);
}

__global__ void gn_var(const float* __restrict__ hbuf, const int* __restrict__ batch,
                       const float* __restrict__ gsum, const float* __restrict__ gcnt,
                       float* __restrict__ gvar) {
    int idx = blockIdx.x * blockDim.x + threadIdx.x;
    int warp = idx >> 5, lane = idx & 31;
    if (warp >= NN) return;
    int g = batch[warp];
    float mean = gsum[g] / (gcnt[g] * DD);
    float4 v = ((const float4*)(hbuf + (size_t)warp * DD))[lane];
    float a = v.x - mean, b = v.y - mean, c = v.z - mean, d = v.w - mean;
    float s = a * a + b * b + c * c + d * d;
#pragma unroll
    for (int o = 16; o; o >>= 1) s += __shfl_xor_sync(0xffffffffu, s, o);
    if (!lane) atomicAdd(&gvar[g], s);
}

__global__ void gn_apply(float* __restrict__ hbuf, const int* __restrict__ batch,
                         const float* __restrict__ gsum, const float* __restrict__ gvar,
                         const float* __restrict__ gcnt) {
    int t = blockIdx.x * blockDim.x + threadIdx.x;
    if (t >= NN * DD) return;
    int n = t >> 7;
    int g = batch[n];
    float inv = 1.f / (gcnt[g] * DD);
    float mean = gsum[g] * inv;
    float var = gvar[g] * inv;
    hbuf[t] = (hbuf[t] - mean) * rsqrtf(var + 1e-8f);
}

__global__ void read_dot(const float* __restrict__ a, const float* __restrict__ w3,
                         const float* __restrict__ b3, float* __restrict__ results) {
    int idx = blockIdx.x * blockDim.x + threadIdx.x;
    int warp = idx >> 5, lane = idx & 31;
    if (warp >= AA) return;
    float4 av = ((const float4*)(a + (size_t)warp * DD))[lane];
    float4 wv = ((const float4*)w3)[lane];
    float s = av.x * wv.x + av.y * wv.y + av.z * wv.z + av.w * wv.w;
#pragma unroll
    for (int o = 16; o; o >>= 1) s += __shfl_xor_sync(0xffffffffu, s, o);
    if (!lane) results[warp] += s + b3[0];
}

__global__ void final_scatter(const float* __restrict__ results, const int* __restrict__ abatch,
                              float* __restrict__ out) {
    int a = blockIdx.x * blockDim.x + threadIdx.x;
    if (a >= AA) return;
    atomicAdd(&out[abatch[a]], results[a] * (1.0f / (float)LL));
}

// ---------------- host orchestration ----------------
static void launch_gemm(const float* A, const float* W, const float* bias,
                        const float* res, const float* mul, float* C,
                        int M, int K, int flags) {
    gemm_bf3<<<(M + 127) / 128, 512>>>(A, W, bias, res, mul, C, M, K, flags);
}

extern "C" void kernel_launch(void* const* d_in, const int* in_sizes, int n_in,
                              void* d_out, int out_size) {
    const float* x         = (const float*)d_in[0];
    const float* node_rbf  = (const float*)d_in[1];
    const float* edge_sbf  = (const float*)d_in[2];
    const int*   eidx      = (const int*)d_in[3];
    const int*   pai       = (const int*)d_in[4];
    const int*   idx0      = (const int*)d_in[5];
    const int*   abatch    = (const int*)d_in[6];
    const int*   nbatch    = (const int*)d_in[7];
    const float* edgenn_w1 = (const float*)d_in[8];
    const float* edgenn_b1 = (const float*)d_in[9];
    const float* edgenn_w2 = (const float*)d_in[10];
    const float* edgenn_b2 = (const float*)d_in[11];
    const float* conv_wq   = (const float*)d_in[12];
    const float* conv_wk   = (const float*)d_in[13];
    const float* conv_wv   = (const float*)d_in[14];
    const float* conv_we   = (const float*)d_in[15];
    const float* conv_wsbf = (const float*)d_in[16];
    const float* conv_bsbf = (const float*)d_in[17];
    const float* conv_wrbf = (const float*)d_in[18];
    const float* dense_w   = (const float*)d_in[19];
    const float* dense_b   = (const float*)d_in[20];
    const float* bf_w      = (const float*)d_in[21];
    const float* bf_b      = (const float*)d_in[22];
    const float* af_w      = (const float*)d_in[23];
    const float* af_b      = (const float*)d_in[24];
    const float* read_wrbf = (const float*)d_in[25];
    const float* read_w1   = (const float*)d_in[26];
    const float* read_b1   = (const float*)d_in[27];
    const float* read_w2   = (const float*)d_in[28];
    const float* read_b2   = (const float*)d_in[29];
    const float* read_w3   = (const float*)d_in[30];
    const float* read_b3   = (const float*)d_in[31];

    float *featA, *featB, *featC, *featD, *featE, *sw;
    float *at1, *at2, *at3, *results, *gsum, *gvar, *gcnt;
    int *eoff, *epos, *ecsr, *aoff, *apos, *acsr;
    cudaGetSymbolAddress((void**)&featA, g_featA);
    cudaGetSymbolAddress((void**)&featB, g_featB);
    cudaGetSymbolAddress((void**)&featC, g_featC);
    cudaGetSymbolAddress((void**)&featD, g_featD);
    cudaGetSymbolAddress((void**)&featE, g_featE);
    cudaGetSymbolAddress((void**)&sw, g_sw);
    cudaGetSymbolAddress((void**)&at1, g_at1);
    cudaGetSymbolAddress((void**)&at2, g_at2);
    cudaGetSymbolAddress((void**)&at3, g_at3);
    cudaGetSymbolAddress((void**)&results, g_results);
    cudaGetSymbolAddress((void**)&gsum, g_gsum);
    cudaGetSymbolAddress((void**)&gvar, g_gvar);
    cudaGetSymbolAddress((void**)&gcnt, g_gcnt);
    cudaGetSymbolAddress((void**)&eoff, g_eoff);
    cudaGetSymbolAddress((void**)&epos, g_epos);
    cudaGetSymbolAddress((void**)&ecsr, g_ecsr);
    cudaGetSymbolAddress((void**)&aoff, g_aoff);
    cudaGetSymbolAddress((void**)&apos, g_apos);
    cudaGetSymbolAddress((void**)&acsr, g_acsr);

    cudaMemsetAsync(results, 0, AA * sizeof(float));
    cudaMemsetAsync(gcnt, 0, GG * sizeof(float));
    cudaMemsetAsync(d_out, 0, GG * sizeof(float));
    count_nodes<<<(NN + 255) / 256, 256>>>(nbatch, gcnt);

    // ---- build CSRs (edge by dst; node by atom idx0) ----
    cudaMemsetAsync(eoff, 0, (NN + 1) * sizeof(int));
    hist_seg<<<(EE + 255) / 256, 256>>>(eidx + EE, EE, eoff);
    scan_offsets<<<1, 1024>>>(eoff, NN);
    cudaMemcpyAsync(epos, eoff, NN * sizeof(int), cudaMemcpyDeviceToDevice);
    fill_csr<<<(EE + 255) / 256, 256>>>(eidx + EE, EE, epos, ecsr);

    cudaMemsetAsync(aoff, 0, (AA + 1) * sizeof(int));
    hist_seg<<<(NN + 255) / 256, 256>>>(idx0, NN, aoff);
    scan_offsets<<<1, 1024>>>(aoff, AA);
    cudaMemcpyAsync(apos, aoff, AA * sizeof(int), cudaMemcpyDeviceToDevice);
    fill_csr<<<(NN + 255) / 256, 256>>>(idx0, NN, apos, acsr);

    // readout helper — featE as gated temp (dead outside)
    auto readout = [&](int i, const float* cur) {
        launch_gemm(node_rbf, read_wrbf + (size_t)i * RBFD * DD, nullptr, nullptr, cur,
                    featE, NN, RBFD, EP_MUL);
        gather_rows_csr<<<(AA * 32 + 255) / 256, 256>>>(featE, aoff, acsr, at1, AA);
        launch_gemm(at1, read_w1 + (size_t)i * DD * DD, read_b1 + (size_t)i * DD,
                    nullptr, nullptr, at2, AA, DD, EP_SILU);
        launch_gemm(at2, read_w2 + (size_t)i * DD * DD, read_b2 + (size_t)i * DD,
                    nullptr, nullptr, at3, AA, DD, EP_SILU);
        read_dot<<<(AA * 32 + 255) / 256, 256>>>(at3, read_w3 + (size_t)i * DD,
                                                 read_b3 + i, results);
    };

    const float* cur = x;
    readout(0, cur);

    for (int i = 0; i < LL; i++) {
        size_t dd = (size_t)i * DD * DD;
        float* kt = (cur == featC) ? featD : featC;  // layer chain temp / output
        // atoms_rep + edge-NN + conv_we on atoms (commute with per-edge gather)
        gather_rows_csr<<<(AA * 32 + 255) / 256, 256>>>(cur, aoff, acsr, at1, AA);
        launch_gemm(at1, edgenn_w1 + dd, edgenn_b1 + (size_t)i * DD, nullptr, nullptr,
                    at2, AA, DD, EP_SILU);
        launch_gemm(at2, edgenn_w2 + dd, edgenn_b2 + (size_t)i * DD, nullptr, nullptr,
                    at3, AA, DD, 0);
        launch_gemm(at3, conv_we + dd, nullptr, nullptr, nullptr, at2, AA, DD, 0);
        // q -> featB, k -> kt, v -> featE
        launch_gemm(cur, conv_wq + dd, nullptr, nullptr, nullptr, featB, NN, DD, 0);
        launch_gemm(cur, conv_wk + dd, nullptr, nullptr, nullptr, kt, NN, DD, 0);
        launch_gemm(cur, conv_wv + dd, nullptr, nullptr, nullptr, featE, NN, DD, 0);
        // sbf modulation weights
        launch_gemm(edge_sbf, conv_wsbf + (size_t)i * SBFD * DD, conv_bsbf + (size_t)i * DD,
                    nullptr, nullptr, sw, EE, SBFD, 0);
        // fused attention (softmax + message aggregation), no atomics -> featA
        attn_csr<<<(NN * 32 + 255) / 256, 256>>>(featB, kt, featE, at2, sw,
                                                 eidx, pai, eoff, ecsr, featA);
        // out = msg * (node_rbf @ conv_wrbf[i]) -> featB (q dead)
        launch_gemm(node_rbf, conv_wrbf + (size_t)i * RBFD * DD, nullptr, nullptr, featA,
                    featB, NN, RBFD, EP_MUL);
        // graph norm in place on featB
        cudaMemsetAsync(gsum, 0, GG * sizeof(float));
        cudaMemsetAsync(gvar, 0, GG * sizeof(float));
        gn_sum<<<(NN * 32 + 255) / 256, 256>>>(featB, nbatch, gsum);
        gn_var<<<(NN * 32 + 255) / 256, 256>>>(featB, nbatch, gsum, gcnt, gvar);
        gn_apply<<<(NN * DD + 255) / 256, 256>>>(featB, nbatch, gsum, gvar, gcnt);
        // bf residual block: featB -> kt -> featB
        launch_gemm(featB, bf_w + (size_t)(i * 2 + 0) * DD * DD, bf_b + (size_t)(i * 2 + 0) * DD,
                    nullptr, nullptr, kt, NN, DD, EP_SILU);
        launch_gemm(kt, bf_w + (size_t)(i * 2 + 1) * DD * DD, bf_b + (size_t)(i * 2 + 1) * DD,
                    featB, nullptr, featB, NN, DD, EP_SILU | EP_RES);
        // dense + residual with layer input (res0 = cur) -> kt
        launch_gemm(featB, dense_w + dd, dense_b + (size_t)i * DD, cur, nullptr,
                    kt, NN, DD, EP_SILU | EP_RES);
        // af residual blocks x2: kt <-> featB, ending in kt
        launch_gemm(kt, af_w + (size_t)(i * 4 + 0) * DD * DD, af_b + (size_t)(i * 4 + 0) * DD,
                    nullptr, nullptr, featB, NN, DD, EP_SILU);
        launch_gemm(featB, af_w + (size_t)(i * 4 + 1) * DD * DD, af_b + (size_t)(i * 4 + 1) * DD,
                    kt, nullptr, kt, NN, DD, EP_SILU | EP_RES);
        launch_gemm(kt, af_w + (size_t)(i * 4 + 2) * DD * DD, af_b + (size_t)(i * 4 + 2) * DD,
                    nullptr, nullptr, featB, NN, DD, EP_SILU);
        launch_gemm(featB, af_w + (size_t)(i * 4 + 3) * DD * DD, af_b + (size_t)(i * 4 + 3) * DD,
                    kt, nullptr, kt, NN, DD, EP_SILU | EP_RES);
        // readout of new features
        readout(i + 1, kt);
        cur = kt;  // ping-pong, no memcpy
    }

    final_scatter<<<(AA + 255) / 256, 256>>>(results, abatch, (float*)d_out);
}

// round 5
// speedup vs baseline: 1.6788x; 1.1443x over previous
#include <cuda_runtime.h>
#include <math.h>
#include <stdint.h>

#define NN 60000
#define EE 300000
#define AA 8000
#define GG 256
#define DD 128
#define HH 8
#define CC 16
#define LL 3
#define RBFD 16
#define SBFD 112

// ---------------- scratch (static device globals; no allocation) ----------------
__device__ float g_featA[NN * DD];
__device__ float g_featB[NN * DD];
__device__ float g_featC[NN * DD];
__device__ float g_featD[NN * DD];
__device__ float g_featE[NN * DD];
__device__ float g_sw[(size_t)EE * DD];
__device__ float g_at1[AA * DD];
__device__ float g_at2[AA * DD];
__device__ float g_at3[AA * DD];
__device__ float g_results[AA];
__device__ float g_gsum[GG];
__device__ float g_gvar[GG];
__device__ float g_gcnt[GG];
// CSR scratch (indices are constant per call; built once, reused)
__device__ int g_eoff[NN + 1];
__device__ int g_epos[NN];
__device__ int g_ecsr[EE];
__device__ int g_aoff[AA + 1];
__device__ int g_apos[AA];
__device__ int g_acsr[NN];

// ---------------- helpers ----------------
__device__ __forceinline__ float silu_f(float v) { return v / (1.f + expf(-v)); }

__device__ __forceinline__ uint32_t pack_bf(float x, float y) {
    uint32_t r;
    asm("cvt.rn.bf16x2.f32 %0, %1, %2;" : "=r"(r) : "f"(y), "f"(x));
    return r;
}
__device__ __forceinline__ float bf_lo(uint32_t u) { return __uint_as_float(u << 16); }
__device__ __forceinline__ float bf_hi(uint32_t u) { return __uint_as_float(u & 0xffff0000u); }

__device__ __forceinline__ void mma_bf16(float* acc, const uint32_t* a, const uint32_t* b) {
    asm volatile(
        "mma.sync.aligned.m16n8k16.row.col.f32.bf16.bf16.f32 "
        "{%0,%1,%2,%3}, {%4,%5,%6,%7}, {%8,%9}, {%0,%1,%2,%3};\n"
        : "+f"(acc[0]), "+f"(acc[1]), "+f"(acc[2]), "+f"(acc[3])
        : "r"(a[0]), "r"(a[1]), "r"(a[2]), "r"(a[3]), "r"(b[0]), "r"(b[1]));
}

__device__ __forceinline__ uint32_t sptr(const void* p) {
    return (uint32_t)__cvta_generic_to_shared(p);
}
#define LDSM4(r0, r1, r2, r3, addr)                                             \
    asm volatile("ldmatrix.sync.aligned.m8n8.x4.shared.b16 {%0,%1,%2,%3}, [%4];" \
                 : "=r"(r0), "=r"(r1), "=r"(r2), "=r"(r3) : "r"(addr))

#define EP_SILU 1
#define EP_RES 2
#define EP_MUL 4

// ---------------- bf16x3 split-precision tensor-core GEMM, N fixed = 128 ----------------
// C[M,128] = ep(A[M,K] @ W[K,128] + bias). K multiple of 16.
// Block 128x128, BK=16 double-buffered, 256 threads = 8 warps (2M x 4N),
// warp tile 64x32. Fragments loaded with ldmatrix.x4 (12 LDSM feed 48 mma).
// Row stride 12 words (48B): 8-row LDSM phases hit all 32 banks exactly once.
#define SAW 12

__global__ __launch_bounds__(256, 2) void gemm_bf3(
    const float* __restrict__ A, const float* __restrict__ W,
    const float* __restrict__ bias, const float* __restrict__ res,
    const float* __restrict__ mul, float* __restrict__ C,
    int M, int K, int flags)
{
    __shared__ uint32_t AsH[2][128][SAW];
    __shared__ uint32_t AsL[2][128][SAW];
    __shared__ uint32_t WsH[2][128][SAW];
    __shared__ uint32_t WsL[2][128][SAW];

    const int tid = threadIdx.x;
    const int wid = tid >> 5, lane = tid & 31;
    const int g = lane >> 2, tig = lane & 3;
    const int m0 = (wid & 1) * 64, n0 = (wid >> 1) * 32;
    const int row0 = blockIdx.x * 128;

    // staging: A row = tid>>1, 8 floats at (tid&1)*8 -> words (tid&1)*4
    const int arow = tid >> 1, akf = (tid & 1) * 8, akw = (tid & 1) * 4;
    // W: col n = tid&127, 8 k's at (tid>>7)*8 -> words (tid>>7)*4
    const int wn = tid & 127, wkb = (tid >> 7) * 8, wkw = (tid >> 7) * 4;

    // ldmatrix addressing
    const int a_r = lane & 15, a_kw = (lane >> 4) * 4;
    const int b_nadd = ((lane >> 4) << 3) | (lane & 7), b_kw = ((lane >> 3) & 1) * 4;

    float acc[4][4][4];
#pragma unroll
    for (int mi = 0; mi < 4; mi++)
#pragma unroll
        for (int ni = 0; ni < 4; ni++)
#pragma unroll
            for (int r = 0; r < 4; r++) acc[mi][ni][r] = 0.f;

    const int nc = K >> 4;
    const bool arow_ok = (row0 + arow) < M;
    const float* aptr = A + (size_t)(row0 + arow) * K + akf;

    float fa[8], fw[8];

    auto fetch = [&](int c) {
        const float* ap = aptr + (size_t)c * 16;
        if (arow_ok) {
            *(float4*)&fa[0] = *(const float4*)ap;
            *(float4*)&fa[4] = *(const float4*)(ap + 4);
        } else {
#pragma unroll
            for (int p = 0; p < 8; p++) fa[p] = 0.f;
        }
        const float* wp = W + (size_t)c * 16 * 128;
#pragma unroll
        for (int j = 0; j < 8; j++) fw[j] = wp[(size_t)(wkb + j) * 128 + wn];
    };
    auto stage = [&](int b) {
        uint32_t h[4], l[4];
#pragma unroll
        for (int p = 0; p < 4; p++) {
            h[p] = pack_bf(fa[2 * p], fa[2 * p + 1]);
            l[p] = pack_bf(fa[2 * p] - bf_lo(h[p]), fa[2 * p + 1] - bf_hi(h[p]));
        }
        *(uint4*)&AsH[b][arow][akw] = make_uint4(h[0], h[1], h[2], h[3]);
        *(uint4*)&AsL[b][arow][akw] = make_uint4(l[0], l[1], l[2], l[3]);
#pragma unroll
        for (int p = 0; p < 4; p++) {
            h[p] = pack_bf(fw[2 * p], fw[2 * p + 1]);
            l[p] = pack_bf(fw[2 * p] - bf_lo(h[p]), fw[2 * p + 1] - bf_hi(h[p]));
        }
        *(uint4*)&WsH[b][wn][wkw] = make_uint4(h[0], h[1], h[2], h[3]);
        *(uint4*)&WsL[b][wn][wkw] = make_uint4(l[0], l[1], l[2], l[3]);
    };

    fetch(0);
    stage(0);
    __syncthreads();

    int cur = 0;
    for (int c = 0; c < nc; c++) {
        const bool pf = (c + 1 < nc);
        if (pf) fetch(c + 1);

        // ---- B fragments: 4 LDSM.x4 ----
        uint32_t bH[4][2], bL[4][2];
#pragma unroll
        for (int hh = 0; hh < 2; hh++) {
            int n = n0 + hh * 16 + b_nadd;
            LDSM4(bH[2 * hh][0], bH[2 * hh][1], bH[2 * hh + 1][0], bH[2 * hh + 1][1],
                  sptr(&WsH[cur][n][b_kw]));
            LDSM4(bL[2 * hh][0], bL[2 * hh][1], bL[2 * hh + 1][0], bL[2 * hh + 1][1],
                  sptr(&WsL[cur][n][b_kw]));
        }
        // ---- A fragments + mma ----
#pragma unroll
        for (int mi = 0; mi < 4; mi++) {
            int r = m0 + mi * 16 + a_r;
            uint32_t aH[4], aL[4];
            LDSM4(aH[0], aH[1], aH[2], aH[3], sptr(&AsH[cur][r][a_kw]));
            LDSM4(aL[0], aL[1], aL[2], aL[3], sptr(&AsL[cur][r][a_kw]));
#pragma unroll
            for (int ni = 0; ni < 4; ni++) {
                mma_bf16(acc[mi][ni], aH, bH[ni]);
                mma_bf16(acc[mi][ni], aH, bL[ni]);
                mma_bf16(acc[mi][ni], aL, bH[ni]);
            }
        }
        if (pf) stage(cur ^ 1);
        __syncthreads();
        cur ^= 1;
    }

    // ---- epilogue (acc rows g/g+8, cols 2*tig, 2*tig+1) ----
#pragma unroll
    for (int mi = 0; mi < 4; mi++) {
        int rbase = row0 + m0 + mi * 16 + g;
#pragma unroll
        for (int ni = 0; ni < 4; ni++) {
            int cidx = n0 + ni * 8 + tig * 2;
#pragma unroll
            for (int half = 0; half < 2; half++) {
                int r = rbase + half * 8;
                if (r >= M) continue;
                float vx = acc[mi][ni][half * 2 + 0];
                float vy = acc[mi][ni][half * 2 + 1];
                if (bias) { vx += bias[cidx]; vy += bias[cidx + 1]; }
                if (flags & EP_SILU) { vx = silu_f(vx); vy = silu_f(vy); }
                size_t off = (size_t)r * 128 + cidx;
                if (flags & EP_RES) {
                    float2 rr = *(const float2*)(res + off);
                    vx += rr.x; vy += rr.y;
                }
                if (flags & EP_MUL) {
                    float2 mm = *(const float2*)(mul + off);
                    vx *= mm.x; vy *= mm.y;
                }
                *(float2*)(C + off) = make_float2(vx, vy);
            }
        }
    }
}

// ---------------- CSR construction (built once per call, indices constant) ----------------
__global__ void hist_seg(const int* __restrict__ idx, int n, int* __restrict__ deg) {
    int t = blockIdx.x * blockDim.x + threadIdx.x;
    if (t >= n) return;
    atomicAdd(&deg[idx[t] + 1], 1);
}

// single-block inclusive scan over deg[1..n]; deg[0] must be 0
__global__ void scan_offsets(int* __restrict__ deg, int n) {
    __shared__ int buf[1024];
    __shared__ int carry;
    if (threadIdx.x == 0) carry = 0;
    __syncthreads();
    for (int base = 0; base < n; base += 1024) {
        int i = base + threadIdx.x;
        int v = (i < n) ? deg[i + 1] : 0;
        buf[threadIdx.x] = v;
        __syncthreads();
        for (int off = 1; off < 1024; off <<= 1) {
            int t = (threadIdx.x >= off) ? buf[threadIdx.x - off] : 0;
            __syncthreads();
            buf[threadIdx.x] += t;
            __syncthreads();
        }
        int total = buf[1023];
        if (i < n) deg[i + 1] = buf[threadIdx.x] + carry;
        __syncthreads();
        if (threadIdx.x == 0) carry += total;
        __syncthreads();
    }
}

__global__ void fill_csr(const int* __restrict__ idx, int n, int* __restrict__ pos,
                         int* __restrict__ csr) {
    int t = blockIdx.x * blockDim.x + threadIdx.x;
    if (t >= n) return;
    int p = atomicAdd(&pos[idx[t]], 1);
    csr[p] = t;
}

// ---------------- CSR gather: dst[a,:] = sum over csr segment of src rows ----------------
__global__ void gather_rows_csr(const float* __restrict__ src, const int* __restrict__ off,
                                const int* __restrict__ csr, float* __restrict__ dst, int nseg) {
    int idx = blockIdx.x * blockDim.x + threadIdx.x;
    int w = idx >> 5, lane = idx & 31;
    if (w >= nseg) return;
    int s = off[w], e = off[w + 1];
    float4 acc = make_float4(0, 0, 0, 0);
    for (int j = s; j < e; j++) {
        int n = csr[j];
        float4 v = ((const float4*)(src + (size_t)n * DD))[lane];
        acc.x += v.x; acc.y += v.y; acc.z += v.z; acc.w += v.w;
    }
    ((float4*)(dst + (size_t)w * DD))[lane] = acc;
}

// ---------------- fused CSR attention: warp per dst node, no atomics ----------------
__global__ void attn_csr(const float* __restrict__ q, const float* __restrict__ k,
                         const float* __restrict__ v, const float* __restrict__ ek,
                         const float* __restrict__ sw, const int* __restrict__ esrc,
                         const int* __restrict__ pai, const int* __restrict__ off,
                         const int* __restrict__ csr, float* __restrict__ out) {
    int idx = blockIdx.x * blockDim.x + threadIdx.x;
    int w = idx >> 5, lane = idx & 31;
    if (w >= NN) return;
    int s0 = off[w], s1 = off[w + 1];
    float4 q4 = ((const float4*)(q + (size_t)w * DD))[lane];

    float mx = -1e30f;
    for (int j = s0; j < s1; j++) {
        int e = csr[j];
        int sn = esrc[e], pa = pai[e];
        float4 k4 = ((const float4*)(k + (size_t)sn * DD))[lane];
        float4 e4 = ((const float4*)(ek + (size_t)pa * DD))[lane];
        float p = q4.x * (k4.x + e4.x) + q4.y * (k4.y + e4.y) +
                  q4.z * (k4.z + e4.z) + q4.w * (k4.w + e4.w);
        p += __shfl_xor_sync(0xffffffffu, p, 1);
        p += __shfl_xor_sync(0xffffffffu, p, 2);
        p *= 0.25f;
        mx = fmaxf(mx, p);
    }

    float4 acc = make_float4(0, 0, 0, 0);
    float den = 0.f;
    for (int j = s0; j < s1; j++) {
        int e = csr[j];
        int sn = esrc[e], pa = pai[e];
        float4 k4 = ((const float4*)(k + (size_t)sn * DD))[lane];
        float4 e4 = ((const float4*)(ek + (size_t)pa * DD))[lane];
        float p = q4.x * (k4.x + e4.x) + q4.y * (k4.y + e4.y) +
                  q4.z * (k4.z + e4.z) + q4.w * (k4.w + e4.w);
        p += __shfl_xor_sync(0xffffffffu, p, 1);
        p += __shfl_xor_sync(0xffffffffu, p, 2);
        p *= 0.25f;
        float ex = expf(p - mx);
        den += ex;
        float4 v4 = ((const float4*)(v + (size_t)sn * DD))[lane];
        float4 s4 = ((const float4*)(sw + (size_t)e * DD))[lane];
        acc.x += ex * (v4.x + e4.x) * s4.x;
        acc.y += ex * (v4.y + e4.y) * s4.y;
        acc.z += ex * (v4.z + e4.z) * s4.z;
        acc.w += ex * (v4.w + e4.w) * s4.w;
    }
    float inv = 1.f / (den + 1e-16f);
    acc.x *= inv; acc.y *= inv; acc.z *= inv; acc.w *= inv;
    ((float4*)(out + (size_t)w * DD))[lane] = acc;
}

// ---------------- norm / readout kernels ----------------
__global__ void count_nodes(const int* __restrict__ batch, float* __restrict__ cnt) {
    int n = blockIdx.x * blockDim.x + threadIdx.x;
    if (n >= NN) return;
    atomicAdd(&cnt[batch[n]], 1.f);
}

__global__ void gn_sum(const float* __restrict__ hbuf, const int* __restrict__ batch,
                       float* __restrict__ gsum) {
    int idx = blockIdx.x * blockDim.x + threadIdx.x;
    int warp = idx >> 5, lane = idx & 31;
    if (warp >= NN) return;
    float4 v = ((const float4*)(hbuf + (size_t)warp * DD))[lane];
    float s = v.x + v.y + v.z + v.w;
#pragma unroll
    for (int o = 16; o; o >>= 1) s += __shfl_xor_sync(0xffffffffu, s, o);
    if (!lane) atomicAdd(&gsum[batch[warp]], s);
}

__global__ void gn_var(const float* __restrict__ hbuf, const int* __restrict__ batch,
                       const float* __restrict__ gsum, const float* __restrict__ gcnt,
                       float* __restrict__ gvar) {
    int idx = blockIdx.x * blockDim.x + threadIdx.x;
    int warp = idx >> 5, lane = idx & 31;
    if (warp >= NN) return;
    int g = batch[warp];
    float mean = gsum[g] / (gcnt[g] * DD);
    float4 v = ((const float4*)(hbuf + (size_t)warp * DD))[lane];
    float a = v.x - mean, b = v.y - mean, c = v.z - mean, d = v.w - mean;
    float s = a * a + b * b + c * c + d * d;
#pragma unroll
    for (int o = 16; o; o >>= 1) s += __shfl_xor_sync(0xffffffffu, s, o);
    if (!lane) atomicAdd(&gvar[g], s);
}

__global__ void gn_apply(float* __restrict__ hbuf, const int* __restrict__ batch,
                         const float* __restrict__ gsum, const float* __restrict__ gvar,
                         const float* __restrict__ gcnt) {
    int t = blockIdx.x * blockDim.x + threadIdx.x;
    if (t >= NN * DD) return;
    int n = t >> 7;
    int g = batch[n];
    float inv = 1.f / (gcnt[g] * DD);
    float mean = gsum[g] * inv;
    float var = gvar[g] * inv;
    hbuf[t] = (hbuf[t] - mean) * rsqrtf(var + 1e-8f);
}

__global__ void read_dot(const float* __restrict__ a, const float* __restrict__ w3,
                         const float* __restrict__ b3, float* __restrict__ results) {
    int idx = blockIdx.x * blockDim.x + threadIdx.x;
    int warp = idx >> 5, lane = idx & 31;
    if (warp >= AA) return;
    float4 av = ((const float4*)(a + (size_t)warp * DD))[lane];
    float4 wv = ((const float4*)w3)[lane];
    float s = av.x * wv.x + av.y * wv.y + av.z * wv.z + av.w * wv.w;
#pragma unroll
    for (int o = 16; o; o >>= 1) s += __shfl_xor_sync(0xffffffffu, s, o);
    if (!lane) results[warp] += s + b3[0];
}

__global__ void final_scatter(const float* __restrict__ results, const int* __restrict__ abatch,
                              float* __restrict__ out) {
    int a = blockIdx.x * blockDim.x + threadIdx.x;
    if (a >= AA) return;
    atomicAdd(&out[abatch[a]], results[a] * (1.0f / (float)LL));
}

// ---------------- host orchestration ----------------
static void launch_gemm(const float* A, const float* W, const float* bias,
                        const float* res, const float* mul, float* C,
                        int M, int K, int flags) {
    gemm_bf3<<<(M + 127) / 128, 256>>>(A, W, bias, res, mul, C, M, K, flags);
}

extern "C" void kernel_launch(void* const* d_in, const int* in_sizes, int n_in,
                              void* d_out, int out_size) {
    const float* x         = (const float*)d_in[0];
    const float* node_rbf  = (const float*)d_in[1];
    const float* edge_sbf  = (const float*)d_in[2];
    const int*   eidx      = (const int*)d_in[3];
    const int*   pai       = (const int*)d_in[4];
    const int*   idx0      = (const int*)d_in[5];
    const int*   abatch    = (const int*)d_in[6];
    const int*   nbatch    = (const int*)d_in[7];
    const float* edgenn_w1 = (const float*)d_in[8];
    const float* edgenn_b1 = (const float*)d_in[9];
    const float* edgenn_w2 = (const float*)d_in[10];
    const float* edgenn_b2 = (const float*)d_in[11];
    const float* conv_wq   = (const float*)d_in[12];
    const float* conv_wk   = (const float*)d_in[13];
    const float* conv_wv   = (const float*)d_in[14];
    const float* conv_we   = (const float*)d_in[15];
    const float* conv_wsbf = (const float*)d_in[16];
    const float* conv_bsbf = (const float*)d_in[17];
    const float* conv_wrbf = (const float*)d_in[18];
    const float* dense_w   = (const float*)d_in[19];
    const float* dense_b   = (const float*)d_in[20];
    const float* bf_w      = (const float*)d_in[21];
    const float* bf_b      = (const float*)d_in[22];
    const float* af_w      = (const float*)d_in[23];
    const float* af_b      = (const float*)d_in[24];
    const float* read_wrbf = (const float*)d_in[25];
    const float* read_w1   = (const float*)d_in[26];
    const float* read_b1   = (const float*)d_in[27];
    const float* read_w2   = (const float*)d_in[28];
    const float* read_b2   = (const float*)d_in[29];
    const float* read_w3   = (const float*)d_in[30];
    const float* read_b3   = (const float*)d_in[31];

    float *featA, *featB, *featC, *featD, *featE, *sw;
    float *at1, *at2, *at3, *results, *gsum, *gvar, *gcnt;
    int *eoff, *epos, *ecsr, *aoff, *apos, *acsr;
    cudaGetSymbolAddress((void**)&featA, g_featA);
    cudaGetSymbolAddress((void**)&featB, g_featB);
    cudaGetSymbolAddress((void**)&featC, g_featC);
    cudaGetSymbolAddress((void**)&featD, g_featD);
    cudaGetSymbolAddress((void**)&featE, g_featE);
    cudaGetSymbolAddress((void**)&sw, g_sw);
    cudaGetSymbolAddress((void**)&at1, g_at1);
    cudaGetSymbolAddress((void**)&at2, g_at2);
    cudaGetSymbolAddress((void**)&at3, g_at3);
    cudaGetSymbolAddress((void**)&results, g_results);
    cudaGetSymbolAddress((void**)&gsum, g_gsum);
    cudaGetSymbolAddress((void**)&gvar, g_gvar);
    cudaGetSymbolAddress((void**)&gcnt, g_gcnt);
    cudaGetSymbolAddress((void**)&eoff, g_eoff);
    cudaGetSymbolAddress((void**)&epos, g_epos);
    cudaGetSymbolAddress((void**)&ecsr, g_ecsr);
    cudaGetSymbolAddress((void**)&aoff, g_aoff);
    cudaGetSymbolAddress((void**)&apos, g_apos);
    cudaGetSymbolAddress((void**)&acsr, g_acsr);

    cudaMemsetAsync(results, 0, AA * sizeof(float));
    cudaMemsetAsync(gcnt, 0, GG * sizeof(float));
    cudaMemsetAsync(d_out, 0, GG * sizeof(float));
    count_nodes<<<(NN + 255) / 256, 256>>>(nbatch, gcnt);

    // ---- build CSRs (edge by dst; node by atom idx0) ----
    cudaMemsetAsync(eoff, 0, (NN + 1) * sizeof(int));
    hist_seg<<<(EE + 255) / 256, 256>>>(eidx + EE, EE, eoff);
    scan_offsets<<<1, 1024>>>(eoff, NN);
    cudaMemcpyAsync(epos, eoff, NN * sizeof(int), cudaMemcpyDeviceToDevice);
    fill_csr<<<(EE + 255) / 256, 256>>>(eidx + EE, EE, epos, ecsr);

    cudaMemsetAsync(aoff, 0, (AA + 1) * sizeof(int));
    hist_seg<<<(NN + 255) / 256, 256>>>(idx0, NN, aoff);
    scan_offsets<<<1, 1024>>>(aoff, AA);
    cudaMemcpyAsync(apos, aoff, AA * sizeof(int), cudaMemcpyDeviceToDevice);
    fill_csr<<<(NN + 255) / 256, 256>>>(idx0, NN, apos, acsr);

    // readout helper — featE as gated temp (dead outside)
    auto readout = [&](int i, const float* cur) {
        launch_gemm(node_rbf, read_wrbf + (size_t)i * RBFD * DD, nullptr, nullptr, cur,
                    featE, NN, RBFD, EP_MUL);
        gather_rows_csr<<<(AA * 32 + 255) / 256, 256>>>(featE, aoff, acsr, at1, AA);
        launch_gemm(at1, read_w1 + (size_t)i * DD * DD, read_b1 + (size_t)i * DD,
                    nullptr, nullptr, at2, AA, DD, EP_SILU);
        launch_gemm(at2, read_w2 + (size_t)i * DD * DD, read_b2 + (size_t)i * DD,
                    nullptr, nullptr, at3, AA, DD, EP_SILU);
        read_dot<<<(AA * 32 + 255) / 256, 256>>>(at3, read_w3 + (size_t)i * DD,
                                                 read_b3 + i, results);
    };

    const float* cur = x;
    readout(0, cur);

    for (int i = 0; i < LL; i++) {
        size_t dd = (size_t)i * DD * DD;
        float* kt = (cur == featC) ? featD : featC;  // layer chain temp / output
        // atoms_rep + edge-NN + conv_we on atoms (commute with per-edge gather)
        gather_rows_csr<<<(AA * 32 + 255) / 256, 256>>>(cur, aoff, acsr, at1, AA);
        launch_gemm(at1, edgenn_w1 + dd, edgenn_b1 + (size_t)i * DD, nullptr, nullptr,
                    at2, AA, DD, EP_SILU);
        launch_gemm(at2, edgenn_w2 + dd, edgenn_b2 + (size_t)i * DD, nullptr, nullptr,
                    at3, AA, DD, 0);
        launch_gemm(at3, conv_we + dd, nullptr, nullptr, nullptr, at2, AA, DD, 0);
        // q -> featB, k -> kt, v -> featE
        launch_gemm(cur, conv_wq + dd, nullptr, nullptr, nullptr, featB, NN, DD, 0);
        launch_gemm(cur, conv_wk + dd, nullptr, nullptr, nullptr, kt, NN, DD, 0);
        launch_gemm(cur, conv_wv + dd, nullptr, nullptr, nullptr, featE, NN, DD, 0);
        // sbf modulation weights
        launch_gemm(edge_sbf, conv_wsbf + (size_t)i * SBFD * DD, conv_bsbf + (size_t)i * DD,
                    nullptr, nullptr, sw, EE, SBFD, 0);
        // fused attention (softmax + message aggregation), no atomics -> featA
        attn_csr<<<(NN * 32 + 255) / 256, 256>>>(featB, kt, featE, at2, sw,
                                                 eidx, pai, eoff, ecsr, featA);
        // out = msg * (node_rbf @ conv_wrbf[i]) -> featB (q dead)
        launch_gemm(node_rbf, conv_wrbf + (size_t)i * RBFD * DD, nullptr, nullptr, featA,
                    featB, NN, RBFD, EP_MUL);
        // graph norm in place on featB
        cudaMemsetAsync(gsum, 0, GG * sizeof(float));
        cudaMemsetAsync(gvar, 0, GG * sizeof(float));
        gn_sum<<<(NN * 32 + 255) / 256, 256>>>(featB, nbatch, gsum);
        gn_var<<<(NN * 32 + 255) / 256, 256>>>(featB, nbatch, gsum, gcnt, gvar);
        gn_apply<<<(NN * DD + 255) / 256, 256>>>(featB, nbatch, gsum, gvar, gcnt);
        // bf residual block: featB -> kt -> featB
        launch_gemm(featB, bf_w + (size_t)(i * 2 + 0) * DD * DD, bf_b + (size_t)(i * 2 + 0) * DD,
                    nullptr, nullptr, kt, NN, DD, EP_SILU);
        launch_gemm(kt, bf_w + (size_t)(i * 2 + 1) * DD * DD, bf_b + (size_t)(i * 2 + 1) * DD,
                    featB, nullptr, featB, NN, DD, EP_SILU | EP_RES);
        // dense + residual with layer input (res0 = cur) -> kt
        launch_gemm(featB, dense_w + dd, dense_b + (size_t)i * DD, cur, nullptr,
                    kt, NN, DD, EP_SILU | EP_RES);
        // af residual blocks x2: kt <-> featB, ending in kt
        launch_gemm(kt, af_w + (size_t)(i * 4 + 0) * DD * DD, af_b + (size_t)(i * 4 + 0) * DD,
                    nullptr, nullptr, featB, NN, DD, EP_SILU);
        launch_gemm(featB, af_w + (size_t)(i * 4 + 1) * DD * DD, af_b + (size_t)(i * 4 + 1) * DD,
                    kt, nullptr, kt, NN, DD, EP_SILU | EP_RES);
        launch_gemm(kt, af_w + (size_t)(i * 4 + 2) * DD * DD, af_b + (size_t)(i * 4 + 2) * DD,
                    nullptr, nullptr, featB, NN, DD, EP_SILU);
        launch_gemm(featB, af_w + (size_t)(i * 4 + 3) * DD * DD, af_b + (size_t)(i * 4 + 3) * DD,
                    kt, nullptr, kt, NN, DD, EP_SILU | EP_RES);
        // readout of new features
        readout(i + 1, kt);
        cur = kt;  // ping-pong, no memcpy
    }

    final_scatter<<<(AA + 255) / 256, 256>>>(results, abatch, (float*)d_out);
}